// round 10
// baseline (speedup 1.0000x reference)
#include <cuda_runtime.h>
#include <cuda_bf16.h>
#include <math.h>
#include <stdint.h>

#define BATCH 2
#define SEQ   2048
#define NEMBD 1024
#define NHEAD 16
#define HSZ   64
#define FFDIM 4096
#define BT    (BATCH*SEQ)      // 4096 rows
#define QKV_LD 3072
#define LN_EPS 1e-5f
#define ATT_SCALE 0.03125f     // 1024^-0.5

// ---------------- scratch (device globals; no allocation allowed) ----------------
__device__ float g_h[(size_t)BT*NEMBD];
__device__ float g_qkv[(size_t)BT*QKV_LD];
__device__ float g_attn[(size_t)BT*NEMBD];
__device__ float g_x2[(size_t)BT*NEMBD];
__device__ float g_f1[(size_t)BT*FFDIM];
__device__ float g_wr[(size_t)12*1024*1024];   // Wqkv_t(3M) Wproj_t(1M) W1_t(4M) W2_t(4M)

// ---------------- helpers ----------------
__device__ __forceinline__ uint32_t f2tf32(float x) {
    uint32_t r;
    asm("cvt.rna.tf32.f32 %0, %1;" : "=r"(r) : "f"(x));
    return r;
}
__device__ __forceinline__ float rndtf(float x) { return __uint_as_float(f2tf32(x)); }

__device__ __forceinline__ void mma_tf32(float* c, const uint32_t* a, const uint32_t* b) {
    asm volatile(
        "mma.sync.aligned.m16n8k8.row.col.f32.tf32.tf32.f32 "
        "{%0,%1,%2,%3}, {%4,%5,%6,%7}, {%8,%9}, {%0,%1,%2,%3};"
        : "+f"(c[0]), "+f"(c[1]), "+f"(c[2]), "+f"(c[3])
        : "r"(a[0]), "r"(a[1]), "r"(a[2]), "r"(a[3]), "r"(b[0]), "r"(b[1]));
}
__device__ __forceinline__ void ldsm_x4(uint32_t& d0, uint32_t& d1, uint32_t& d2, uint32_t& d3,
                                        uint32_t saddr) {
    asm volatile("ldmatrix.sync.aligned.m8n8.x4.shared.b16 {%0,%1,%2,%3}, [%4];"
                 : "=r"(d0), "=r"(d1), "=r"(d2), "=r"(d3) : "r"(saddr));
}
__device__ __forceinline__ void cp_async16(uint32_t saddr, const void* gaddr) {
    asm volatile("cp.async.cg.shared.global [%0], [%1], 16;" :: "r"(saddr), "l"(gaddr));
}
__device__ __forceinline__ void cp_commit() {
    asm volatile("cp.async.commit_group;");
}
template<int N>
__device__ __forceinline__ void cp_wait() {
    asm volatile("cp.async.wait_group %0;" :: "n"(N));
}
__device__ __forceinline__ uint32_t smem_u32(const void* p) {
    return (uint32_t)__cvta_generic_to_shared(p);
}

// ---------------- weight transpose + tf32 round: in [K][N] -> out [N][K] ----------------
__global__ void transpose_round(const float* __restrict__ in, float* __restrict__ out,
                                int K, int N)
{
    __shared__ float t[32][33];
    int kb = blockIdx.y*32, nb = blockIdx.x*32;
    int tx = threadIdx.x, ty = threadIdx.y;   // (32, 8)
    #pragma unroll
    for (int i=0;i<32;i+=8)
        t[ty+i][tx] = in[(long long)(kb+ty+i)*N + nb+tx];
    __syncthreads();
    #pragma unroll
    for (int i=0;i<32;i+=8)
        out[(long long)(nb+ty+i)*K + kb+tx] = rndtf(t[tx][ty+i]);
}

// ---------------- LayerNorm: one block per row; output rounded to tf32 ----------------
__global__ void ln_kernel(const float* __restrict__ x, const float* __restrict__ w,
                          const float* __restrict__ b, float* __restrict__ out)
{
    int row = blockIdx.x;
    const float4* xr = (const float4*)(x + (size_t)row*NEMBD);
    int t = threadIdx.x;
    float4 v = xr[t];
    float s  = v.x + v.y + v.z + v.w;
    float s2 = v.x*v.x + v.y*v.y + v.z*v.z + v.w*v.w;
    #pragma unroll
    for (int o = 16; o > 0; o >>= 1) {
        s  += __shfl_xor_sync(0xffffffffu, s,  o);
        s2 += __shfl_xor_sync(0xffffffffu, s2, o);
    }
    __shared__ float ss[8], ss2[8];
    int wid = t >> 5, lid = t & 31;
    if (lid == 0) { ss[wid] = s; ss2[wid] = s2; }
    __syncthreads();
    if (wid == 0) {
        float a  = (lid < 8) ? ss[lid]  : 0.f;
        float a2 = (lid < 8) ? ss2[lid] : 0.f;
        #pragma unroll
        for (int o = 4; o > 0; o >>= 1) {
            a  += __shfl_xor_sync(0xffffffffu, a,  o);
            a2 += __shfl_xor_sync(0xffffffffu, a2, o);
        }
        if (lid == 0) { ss[0] = a; ss2[0] = a2; }
    }
    __syncthreads();
    float mu  = ss[0]  * (1.0f/NEMBD);
    float var = ss2[0] * (1.0f/NEMBD) - mu*mu;
    float inv = rsqrtf(var + LN_EPS);
    const float4 wv = ((const float4*)w)[t];
    const float4 bv = ((const float4*)b)[t];
    float4 o4;
    o4.x = rndtf((v.x - mu)*inv*wv.x + bv.x);
    o4.y = rndtf((v.y - mu)*inv*wv.y + bv.y);
    o4.z = rndtf((v.z - mu)*inv*wv.z + bv.z);
    o4.w = rndtf((v.w - mu)*inv*wv.w + bv.w);
    ((float4*)(out + (size_t)row*NEMBD))[t] = o4;
}

// ---------------- tf32 tensor-core GEMM: ldmatrix both operands, B pre-transposed ----------------
// C[m,n] = sum_k A[m,k]*Bt[n,k]  (+bias)(relu)(+res). A,Bt tf32-rounded.
// 128x128 block, 8 warps of 64x32 (2x4), BK=16, cp.async multi-stage. 256 threads, occ 2.
template<int STAGES>
__global__ void __launch_bounds__(256, 2)
mma_gemm(const float* __restrict__ A, const float* __restrict__ Bt,
         const float* __restrict__ bias, const float* __restrict__ res,
         float* __restrict__ C,
         int M, int N, int K, int lda, int ldc,
         float alpha, int relu, int round_out)
{
    constexpr int BM = 128, BN = 128, BK = 16;
    constexpr int S20 = BK + 4;           // 20-word row stride (LDSM conflict-free)
    constexpr int MT = 4, NT = 4;

    extern __shared__ float smem[];
    float* Asf = smem;                          // [STAGES][BM][S20]
    float* Bsf = smem + (size_t)STAGES*BM*S20;  // [STAGES][BN][S20]

    int tid = threadIdx.x;
    int wid = tid >> 5;
    int lane = tid & 31;
    int grp = lane >> 2;
    int qid = lane & 3;
    int warpRow = wid >> 2;      // 0..1 -> 64 rows each
    int warpCol = wid & 3;       // 0..3 -> 32 cols each

    int row0 = blockIdx.y * BM;
    int col0 = blockIdx.x * BN;

    uint32_t sA = smem_u32(Asf);
    uint32_t sB = smem_u32(Bsf);

    int r_lane = lane & 15;
    int k_lane = (lane >> 4) << 2;

    float acc[MT][NT][4];
    #pragma unroll
    for (int i=0;i<MT;i++)
        #pragma unroll
        for (int j=0;j<NT;j++) {
            acc[i][j][0]=0.f; acc[i][j][1]=0.f; acc[i][j][2]=0.f; acc[i][j][3]=0.f;
        }

    int nIter = K / BK;

    // staging: 512 16B-chunks each for A and B, 256 threads -> 2 iters each
    auto issue = [&](int s, int buf) {
        #pragma unroll
        for (int t=0; t<2; t++) {
            int ch = tid + t*256;
            int r = ch >> 2;
            int c = (ch & 3) << 2;
            cp_async16(sA + (((buf*BM + r)*S20 + c) << 2),
                       A + (long long)(row0 + r)*lda + s*BK + c);
        }
        #pragma unroll
        for (int t=0; t<2; t++) {
            int ch = tid + t*256;
            int n = ch >> 2;
            int c = (ch & 3) << 2;
            cp_async16(sB + (((buf*BN + n)*S20 + c) << 2),
                       Bt + (long long)(col0 + n)*K + s*BK + c);
        }
    };

    #pragma unroll
    for (int s=0; s<STAGES-1; s++) {
        if (s < nIter) issue(s, s);
        cp_commit();
    }

    for (int it = 0; it < nIter; it++) {
        cp_wait<STAGES-2>();
        __syncthreads();

        int cur = it % STAGES;
        int nx = it + STAGES - 1;
        if (nx < nIter) issue(nx, nx % STAGES);
        cp_commit();

        uint32_t sAc = sA + ((cur*BM)*S20 << 2);
        uint32_t sBc = sB + ((cur*BN)*S20 << 2);

        #pragma unroll
        for (int ks = 0; ks < 2; ks++) {
            int kb = ks*8;
            uint32_t af[MT][4];
            uint32_t bf[NT][2];
            #pragma unroll
            for (int mt=0; mt<MT; mt++) {
                uint32_t ad = sAc + (((warpRow*64 + mt*16 + r_lane)*S20 + kb + k_lane) << 2);
                ldsm_x4(af[mt][0], af[mt][1], af[mt][2], af[mt][3], ad);
            }
            #pragma unroll
            for (int j=0; j<2; j++) {
                uint32_t bd = sBc + (((warpCol*32 + j*16 + r_lane)*S20 + kb + k_lane) << 2);
                ldsm_x4(bf[2*j][0], bf[2*j+1][0], bf[2*j][1], bf[2*j+1][1], bd);
            }
            #pragma unroll
            for (int mt=0; mt<MT; mt++)
                #pragma unroll
                for (int nt=0; nt<NT; nt++)
                    mma_tf32(acc[mt][nt], af[mt], bf[nt]);
        }
        __syncthreads();
    }

    #pragma unroll
    for (int mt=0; mt<MT; mt++) {
        int rA = row0 + warpRow*64 + mt*16 + grp;
        int rB = rA + 8;
        #pragma unroll
        for (int nt=0; nt<NT; nt++) {
            int c = col0 + warpCol*32 + nt*8 + qid*2;
            float v0 = acc[mt][nt][0]*alpha;
            float v1 = acc[mt][nt][1]*alpha;
            float v2 = acc[mt][nt][2]*alpha;
            float v3 = acc[mt][nt][3]*alpha;
            if (bias) {
                float2 bb2 = *(const float2*)(bias + c);
                v0 += bb2.x; v1 += bb2.y; v2 += bb2.x; v3 += bb2.y;
            }
            if (relu) {
                v0 = fmaxf(v0,0.f); v1 = fmaxf(v1,0.f);
                v2 = fmaxf(v2,0.f); v3 = fmaxf(v3,0.f);
            }
            if (res) {
                float2 rA2 = *(const float2*)(res + (long long)rA*ldc + c);
                float2 rB2 = *(const float2*)(res + (long long)rB*ldc + c);
                v0 += rA2.x; v1 += rA2.y; v2 += rB2.x; v3 += rB2.y;
            }
            if (round_out) {
                v0 = rndtf(v0); v1 = rndtf(v1); v2 = rndtf(v2); v3 = rndtf(v3);
            }
            *(float2*)(C + (long long)rA*ldc + c) = make_float2(v0, v1);
            *(float2*)(C + (long long)rB*ldc + c) = make_float2(v2, v3);
        }
    }
}

// ---------------- fused flash attention (tf32 mma), causal ----------------
// qkv combined [BT][3072]: q at +0, k at +1024, v at +2048 (all tf32-rounded).
#define QT_S 136
#define KT_S 72
#define VS_S 72
#define PS_S 72
#define FA_SMEM ((64*QT_S + 64*KT_S + 64*VS_S + 128*PS_S)*4)   // 108544 B

__global__ void __launch_bounds__(256, 1)
flash_kernel(const float* __restrict__ qkv, float* __restrict__ attn)
{
    extern __shared__ float fs[];
    float* Qt = fs;                       // [64][QT_S]  (d, row)
    float* Kt = Qt + 64*QT_S;             // [64][KT_S]  (d, s)
    float* Vs = Kt + 64*KT_S;             // [64][VS_S]  (s, d)
    float* Ps = Vs + 64*VS_S;             // [128][PS_S] (row, s)

    int q0 = blockIdx.x * 128;
    int bh = blockIdx.y;
    int b = bh >> 4, h = bh & 15;
    const float* Qg = qkv + (long long)b*SEQ*QKV_LD + h*HSZ;
    const float* Kg = Qg + NEMBD;
    const float* Vg = Qg + 2*NEMBD;

    int tid = threadIdx.x;
    int wid = tid >> 5;
    int lane = tid & 31;
    int grp = lane >> 2;
    int qid = lane & 3;
    int w16 = wid * 16;

    {
        int r  = tid & 127;
        int cb = (tid >> 7) * 4;
        #pragma unroll
        for (int p = 0; p < 8; p++) {
            int c4 = cb + p*8;
            float4 vv = *(const float4*)(Qg + (long long)(q0 + r)*QKV_LD + c4);
            Qt[(c4+0)*QT_S + r] = vv.x;
            Qt[(c4+1)*QT_S + r] = vv.y;
            Qt[(c4+2)*QT_S + r] = vv.z;
            Qt[(c4+3)*QT_S + r] = vv.w;
        }
    }

    float m0 = -INFINITY, m1 = -INFINITY, l0 = 0.f, l1 = 0.f;
    float O[8][4];
    #pragma unroll
    for (int nt=0; nt<8; nt++) { O[nt][0]=0.f; O[nt][1]=0.f; O[nt][2]=0.f; O[nt][3]=0.f; }

    int t0 = q0 + w16 + grp;
    int t1 = t0 + 8;
    int nkv = q0/64 + 2;

    for (int kj = 0; kj < nkv; kj++) {
        int s0 = kj * 64;
        __syncthreads();

        {
            int r  = tid & 63;
            int cb = (tid >> 6) * 4;
            #pragma unroll
            for (int p = 0; p < 4; p++) {
                int c4 = cb + p*16;
                float4 vv = *(const float4*)(Kg + (long long)(s0 + r)*QKV_LD + c4);
                Kt[(c4+0)*KT_S + r] = vv.x;
                Kt[(c4+1)*KT_S + r] = vv.y;
                Kt[(c4+2)*KT_S + r] = vv.z;
                Kt[(c4+3)*KT_S + r] = vv.w;
            }
        }
        for (int ch = tid; ch < 64*16; ch += 256) {
            int r = ch >> 4, c4 = (ch & 15) << 2;
            float4 vv = *(const float4*)(Vg + (long long)(s0 + r)*QKV_LD + c4);
            *(float4*)&Vs[r*VS_S + c4] = vv;
        }
        __syncthreads();

        float sacc[8][4];
        #pragma unroll
        for (int nt=0; nt<8; nt++) { sacc[nt][0]=0.f; sacc[nt][1]=0.f; sacc[nt][2]=0.f; sacc[nt][3]=0.f; }

        const uint32_t* Qtu = (const uint32_t*)Qt;
        const uint32_t* Ktu = (const uint32_t*)Kt;
        #pragma unroll
        for (int ks = 0; ks < 8; ks++) {
            int kb = ks*8;
            uint32_t a[4];
            a[0] = Qtu[(kb+qid  )*QT_S + w16 + grp    ];
            a[1] = Qtu[(kb+qid  )*QT_S + w16 + grp + 8];
            a[2] = Qtu[(kb+qid+4)*QT_S + w16 + grp    ];
            a[3] = Qtu[(kb+qid+4)*QT_S + w16 + grp + 8];
            #pragma unroll
            for (int nt=0; nt<8; nt++) {
                uint32_t bb[2];
                bb[0] = Ktu[(kb+qid  )*KT_S + nt*8 + grp];
                bb[1] = Ktu[(kb+qid+4)*KT_S + nt*8 + grp];
                mma_tf32(sacc[nt], a, bb);
            }
        }

        #pragma unroll
        for (int nt=0; nt<8; nt++) {
            int c = s0 + nt*8 + 2*qid;
            sacc[nt][0] = (c   <= t0) ? sacc[nt][0]*ATT_SCALE : -INFINITY;
            sacc[nt][1] = (c+1 <= t0) ? sacc[nt][1]*ATT_SCALE : -INFINITY;
            sacc[nt][2] = (c   <= t1) ? sacc[nt][2]*ATT_SCALE : -INFINITY;
            sacc[nt][3] = (c+1 <= t1) ? sacc[nt][3]*ATT_SCALE : -INFINITY;
        }

        float ml0 = -INFINITY, ml1 = -INFINITY;
        #pragma unroll
        for (int nt=0; nt<8; nt++) {
            ml0 = fmaxf(ml0, fmaxf(sacc[nt][0], sacc[nt][1]));
            ml1 = fmaxf(ml1, fmaxf(sacc[nt][2], sacc[nt][3]));
        }
        ml0 = fmaxf(ml0, __shfl_xor_sync(0xffffffffu, ml0, 1));
        ml0 = fmaxf(ml0, __shfl_xor_sync(0xffffffffu, ml0, 2));
        ml1 = fmaxf(ml1, __shfl_xor_sync(0xffffffffu, ml1, 1));
        ml1 = fmaxf(ml1, __shfl_xor_sync(0xffffffffu, ml1, 2));

        float mn0 = fmaxf(m0, ml0);
        float mn1 = fmaxf(m1, ml1);
        float al0 = __expf(m0 - mn0);
        float al1 = __expf(m1 - mn1);

        float sum0 = 0.f, sum1 = 0.f;
        #pragma unroll
        for (int nt=0; nt<8; nt++) {
            float p00 = __expf(sacc[nt][0] - mn0);
            float p01 = __expf(sacc[nt][1] - mn0);
            float p10 = __expf(sacc[nt][2] - mn1);
            float p11 = __expf(sacc[nt][3] - mn1);
            sum0 += p00 + p01;
            sum1 += p10 + p11;
            *(float2*)&Ps[(w16+grp  )*PS_S + nt*8 + 2*qid] = make_float2(rndtf(p00), rndtf(p01));
            *(float2*)&Ps[(w16+grp+8)*PS_S + nt*8 + 2*qid] = make_float2(rndtf(p10), rndtf(p11));
        }
        sum0 += __shfl_xor_sync(0xffffffffu, sum0, 1);
        sum0 += __shfl_xor_sync(0xffffffffu, sum0, 2);
        sum1 += __shfl_xor_sync(0xffffffffu, sum1, 1);
        sum1 += __shfl_xor_sync(0xffffffffu, sum1, 2);

        l0 = l0*al0 + sum0;
        l1 = l1*al1 + sum1;
        #pragma unroll
        for (int nt=0; nt<8; nt++) {
            O[nt][0] *= al0; O[nt][1] *= al0;
            O[nt][2] *= al1; O[nt][3] *= al1;
        }
        m0 = mn0; m1 = mn1;
        __syncthreads();

        const uint32_t* Psu = (const uint32_t*)Ps;
        const uint32_t* Vsu = (const uint32_t*)Vs;
        #pragma unroll
        for (int ks = 0; ks < 8; ks++) {
            int kb = ks*8;
            uint32_t a[4];
            a[0] = Psu[(w16+grp  )*PS_S + kb + qid    ];
            a[1] = Psu[(w16+grp+8)*PS_S + kb + qid    ];
            a[2] = Psu[(w16+grp  )*PS_S + kb + qid + 4];
            a[3] = Psu[(w16+grp+8)*PS_S + kb + qid + 4];
            #pragma unroll
            for (int nt=0; nt<8; nt++) {
                uint32_t bb[2];
                bb[0] = Vsu[(kb+qid  )*VS_S + nt*8 + grp];
                bb[1] = Vsu[(kb+qid+4)*VS_S + nt*8 + grp];
                mma_tf32(O[nt], a, bb);
            }
        }
    }

    float inv0 = 1.0f / l0;
    float inv1 = 1.0f / l1;
    float* outA = attn + ((long long)(b*SEQ + t0))*NEMBD + h*HSZ;
    float* outB = attn + ((long long)(b*SEQ + t1))*NEMBD + h*HSZ;
    #pragma unroll
    for (int nt=0; nt<8; nt++) {
        int c = nt*8 + 2*qid;
        *(float2*)(outA + c) = make_float2(rndtf(O[nt][0]*inv0), rndtf(O[nt][1]*inv0));
        *(float2*)(outB + c) = make_float2(rndtf(O[nt][2]*inv1), rndtf(O[nt][3]*inv1));
    }
}

// ---------------- launch ----------------
extern "C" void kernel_launch(void* const* d_in, const int* in_sizes, int n_in,
                              void* d_out, int out_size)
{
    const float* x     = (const float*)d_in[0];
    const float* Wq    = (const float*)d_in[1];
    const float* Wk    = (const float*)d_in[2];
    const float* Wv    = (const float*)d_in[3];
    const float* Wproj = (const float*)d_in[4];
    const float* bproj = (const float*)d_in[5];
    const float* W1    = (const float*)d_in[6];
    const float* b1    = (const float*)d_in[7];
    const float* W2    = (const float*)d_in[8];
    const float* b2    = (const float*)d_in[9];
    const float* ln1w  = (const float*)d_in[10];
    const float* ln1b  = (const float*)d_in[11];
    const float* ln2w  = (const float*)d_in[12];
    const float* ln2b  = (const float*)d_in[13];
    float* out = (float*)d_out;

    float *ph, *pqkv, *pattn, *px2, *pf1, *pwr;
    cudaGetSymbolAddress((void**)&ph,    g_h);
    cudaGetSymbolAddress((void**)&pqkv,  g_qkv);
    cudaGetSymbolAddress((void**)&pattn, g_attn);
    cudaGetSymbolAddress((void**)&px2,   g_x2);
    cudaGetSymbolAddress((void**)&pf1,   g_f1);
    cudaGetSymbolAddress((void**)&pwr,   g_wr);

    const size_t M1 = (size_t)1024*1024;
    float* Wqkvt = pwr;            // [3072][1024]
    float* Wpt   = pwr + 3*M1;     // [1024][1024]
    float* W1t   = pwr + 4*M1;     // [4096][1024]
    float* W2t   = pwr + 8*M1;     // [1024][4096]

    constexpr int ST = 4;
    constexpr size_t SMEM_G = (size_t)ST*(128*20 + 128*20)*4;   // 81920 B

    auto* kern = mma_gemm<ST>;
    cudaFuncSetAttribute(kern, cudaFuncAttributeMaxDynamicSharedMemorySize, (int)SMEM_G);
    cudaFuncSetAttribute(flash_kernel, cudaFuncAttributeMaxDynamicSharedMemorySize, FA_SMEM);

    // 0) transpose + tf32-round all weights (once per replay)
    {
        dim3 blk(32, 8);
        transpose_round<<<dim3(32, 32),  blk>>>(Wq,    Wqkvt,        1024, 1024);
        transpose_round<<<dim3(32, 32),  blk>>>(Wk,    Wqkvt + M1,   1024, 1024);
        transpose_round<<<dim3(32, 32),  blk>>>(Wv,    Wqkvt + 2*M1, 1024, 1024);
        transpose_round<<<dim3(32, 32),  blk>>>(Wproj, Wpt,          1024, 1024);
        transpose_round<<<dim3(128, 32), blk>>>(W1,    W1t,          1024, 4096);
        transpose_round<<<dim3(32, 128), blk>>>(W2,    W2t,          4096, 1024);
    }

    // 1) LN1 (tf32-rounded)
    ln_kernel<<<BT, 256>>>(x, ln1w, ln1b, ph);

    // 2) fused QKV projection: [BT,1024] @ [1024,3072] -> g_qkv (tf32-rounded)
    kern<<<dim3(QKV_LD/128, BT/128), 256, SMEM_G>>>(ph, Wqkvt, nullptr, nullptr, pqkv,
        BT, QKV_LD, NEMBD, NEMBD, QKV_LD, 1.0f, 0, 1);

    // 3) fused flash attention -> g_attn (tf32-rounded)
    flash_kernel<<<dim3(SEQ/128, BATCH*NHEAD), 256, FA_SMEM>>>(pqkv, pattn);

    // 4) x2 = x + attn @ Wproj + bproj
    kern<<<dim3(NEMBD/128, BT/128), 256, SMEM_G>>>(pattn, Wpt, bproj, x, px2,
        BT, NEMBD, NEMBD, NEMBD, NEMBD, 1.0f, 0, 0);

    // 5) LN2 (tf32-rounded)
    ln_kernel<<<BT, 256>>>(px2, ln2w, ln2b, ph);

    // 6) f1 = relu(h2 @ W1 + b1) (tf32-rounded)
    kern<<<dim3(FFDIM/128, BT/128), 256, SMEM_G>>>(ph, W1t, b1, nullptr, pf1,
        BT, FFDIM, NEMBD, NEMBD, FFDIM, 1.0f, 1, 1);

    // 7) out = x2 + f1 @ W2 + b2
    kern<<<dim3(NEMBD/128, BT/128), 256, SMEM_G>>>(pf1, W2t, b2, px2, out,
        BT, NEMBD, FFDIM, FFDIM, NEMBD, 1.0f, 0, 0);
}

// round 11
// speedup vs baseline: 1.1374x; 1.1374x over previous
#include <cuda_runtime.h>
#include <cuda_bf16.h>
#include <math.h>
#include <stdint.h>

#define BATCH 2
#define SEQ   2048
#define NEMBD 1024
#define NHEAD 16
#define HSZ   64
#define FFDIM 4096
#define BT    (BATCH*SEQ)      // 4096 rows
#define QKV_LD 3072
#define LN_EPS 1e-5f
#define ATT_SCALE 0.03125f     // 1024^-0.5

// ---------------- scratch (device globals; no allocation allowed) ----------------
__device__ float g_h[(size_t)BT*NEMBD];
__device__ float g_qkv[(size_t)BT*QKV_LD];
__device__ float g_attn[(size_t)BT*NEMBD];
__device__ float g_x2[(size_t)BT*NEMBD];
__device__ float g_f1[(size_t)BT*FFDIM];
__device__ float g_wr[(size_t)12*1024*1024];   // Wqkv[1024][3072](3M) Wproj(1M) W1(4M) W2(4M)

// ---------------- helpers ----------------
__device__ __forceinline__ uint32_t f2tf32(float x) {
    uint32_t r;
    asm("cvt.rna.tf32.f32 %0, %1;" : "=r"(r) : "f"(x));
    return r;
}
__device__ __forceinline__ float rndtf(float x) { return __uint_as_float(f2tf32(x)); }

__device__ __forceinline__ void mma_tf32(float* c, const uint32_t* a, const uint32_t* b) {
    asm volatile(
        "mma.sync.aligned.m16n8k8.row.col.f32.tf32.tf32.f32 "
        "{%0,%1,%2,%3}, {%4,%5,%6,%7}, {%8,%9}, {%0,%1,%2,%3};"
        : "+f"(c[0]), "+f"(c[1]), "+f"(c[2]), "+f"(c[3])
        : "r"(a[0]), "r"(a[1]), "r"(a[2]), "r"(a[3]), "r"(b[0]), "r"(b[1]));
}
__device__ __forceinline__ void cp_async16(uint32_t saddr, const void* gaddr) {
    asm volatile("cp.async.cg.shared.global [%0], [%1], 16;" :: "r"(saddr), "l"(gaddr));
}
__device__ __forceinline__ void cp_commit() {
    asm volatile("cp.async.commit_group;");
}
template<int N>
__device__ __forceinline__ void cp_wait() {
    asm volatile("cp.async.wait_group %0;" :: "n"(N));
}
__device__ __forceinline__ uint32_t smem_u32(const void* p) {
    return (uint32_t)__cvta_generic_to_shared(p);
}

// ---------------- weight rounding (fp32 -> tf32-rounded fp32), strided output ----------------
// in: [rows][cols] contiguous; out: row r at out + r*ldo (col offset folded into out ptr)
__global__ void round_w_strided(const float* __restrict__ in, float* __restrict__ out,
                                int cols4, int ldo, int n4)
{
    int i = blockIdx.x*blockDim.x + threadIdx.x;
    if (i < n4) {
        int r  = i / cols4;
        int c4 = i % cols4;
        float4 v = ((const float4*)in)[i];
        v.x = rndtf(v.x); v.y = rndtf(v.y); v.z = rndtf(v.z); v.w = rndtf(v.w);
        *(float4*)(out + (long long)r*ldo + c4*4) = v;
    }
}

// ---------------- LayerNorm: one block per row; output rounded to tf32 ----------------
__global__ void ln_kernel(const float* __restrict__ x, const float* __restrict__ w,
                          const float* __restrict__ b, float* __restrict__ out)
{
    int row = blockIdx.x;
    const float4* xr = (const float4*)(x + (size_t)row*NEMBD);
    int t = threadIdx.x;
    float4 v = xr[t];
    float s  = v.x + v.y + v.z + v.w;
    float s2 = v.x*v.x + v.y*v.y + v.z*v.z + v.w*v.w;
    #pragma unroll
    for (int o = 16; o > 0; o >>= 1) {
        s  += __shfl_xor_sync(0xffffffffu, s,  o);
        s2 += __shfl_xor_sync(0xffffffffu, s2, o);
    }
    __shared__ float ss[8], ss2[8];
    int wid = t >> 5, lid = t & 31;
    if (lid == 0) { ss[wid] = s; ss2[wid] = s2; }
    __syncthreads();
    if (wid == 0) {
        float a  = (lid < 8) ? ss[lid]  : 0.f;
        float a2 = (lid < 8) ? ss2[lid] : 0.f;
        #pragma unroll
        for (int o = 4; o > 0; o >>= 1) {
            a  += __shfl_xor_sync(0xffffffffu, a,  o);
            a2 += __shfl_xor_sync(0xffffffffu, a2, o);
        }
        if (lid == 0) { ss[0] = a; ss2[0] = a2; }
    }
    __syncthreads();
    float mu  = ss[0]  * (1.0f/NEMBD);
    float var = ss2[0] * (1.0f/NEMBD) - mu*mu;
    float inv = rsqrtf(var + LN_EPS);
    const float4 wv = ((const float4*)w)[t];
    const float4 bv = ((const float4*)b)[t];
    float4 o4;
    o4.x = rndtf((v.x - mu)*inv*wv.x + bv.x);
    o4.y = rndtf((v.y - mu)*inv*wv.y + bv.y);
    o4.z = rndtf((v.z - mu)*inv*wv.z + bv.z);
    o4.w = rndtf((v.w - mu)*inv*wv.w + bv.w);
    ((float4*)(out + (size_t)row*NEMBD))[t] = o4;
}

// ---------------- tf32 tensor-core GEMM, cp.async pipeline (R8 proven template) ----------------
// Inputs A and B must already be tf32-rounded. B row-major [K][N].
template<int BM,int BN,int BK,int WM,int WN,int STAGES>
__global__ void __launch_bounds__(((BM/WM)*(BN/WN))*32, 2)
mma_gemm(const float* __restrict__ A, const float* __restrict__ Bm,
         const float* __restrict__ bias, const float* __restrict__ res,
         float* __restrict__ C,
         int M, int N, int K, int lda, int ldb, int ldc,
         float alpha, int relu, int round_out)
{
    constexpr int WARPS_M = BM/WM;
    constexpr int WARPS_N = BN/WN;
    constexpr int THREADS = WARPS_M*WARPS_N*32;
    constexpr int MT = WM/16;
    constexpr int NT = WN/8;
    constexpr int A_STRIDE = BK + 4;
    constexpr int B_STRIDE = BN + 8;

    constexpr int A_CHUNKS = BM*(BK/4);
    constexpr int B_CHUNKS = BK*(BN/4);
    constexpr int A_ITERS  = A_CHUNKS / THREADS;
    constexpr int B_ITERS  = (B_CHUNKS + THREADS - 1) / THREADS;

    extern __shared__ float smem[];
    float* Asf = smem;
    float* Bsf = smem + (size_t)STAGES*BM*A_STRIDE;

    int tid = threadIdx.x;
    int wid = tid >> 5;
    int lane = tid & 31;
    int grp = lane >> 2;
    int qid = lane & 3;
    int warpRow = wid / WARPS_N;
    int warpCol = wid % WARPS_N;

    int row0 = blockIdx.y * BM;
    int col0 = blockIdx.x * BN;

    uint32_t sA = smem_u32(Asf);
    uint32_t sB = smem_u32(Bsf);

    float acc[MT][NT][4];
    #pragma unroll
    for (int i=0;i<MT;i++)
        #pragma unroll
        for (int j=0;j<NT;j++) {
            acc[i][j][0]=0.f; acc[i][j][1]=0.f; acc[i][j][2]=0.f; acc[i][j][3]=0.f;
        }

    int nIter = K / BK;

    auto issue = [&](int s, int buf) {
        #pragma unroll
        for (int t=0; t<A_ITERS; t++) {
            int ch = tid + t*THREADS;
            int r = ch / (BK/4);
            int c = (ch % (BK/4)) * 4;
            cp_async16(sA + (((buf*BM + r)*A_STRIDE + c) << 2),
                       A + (long long)(row0 + r)*lda + s*BK + c);
        }
        #pragma unroll
        for (int t=0; t<B_ITERS; t++) {
            int ch = tid + t*THREADS;
            if (B_CHUNKS % THREADS == 0 || ch < B_CHUNKS) {
                int r = ch / (BN/4);
                int c = (ch % (BN/4)) * 4;
                cp_async16(sB + (((buf*BK + r)*B_STRIDE + c) << 2),
                           Bm + (long long)(s*BK + r)*ldb + col0 + c);
            }
        }
    };

    #pragma unroll
    for (int s=0; s<STAGES-1; s++) {
        if (s < nIter) issue(s, s);
        cp_commit();
    }

    for (int it = 0; it < nIter; it++) {
        cp_wait<STAGES-2>();
        __syncthreads();

        int cur = it % STAGES;
        int nx = it + STAGES - 1;
        if (nx < nIter) issue(nx, nx % STAGES);
        cp_commit();

        const uint32_t* Acur = (const uint32_t*)(Asf + (size_t)cur*BM*A_STRIDE);
        const uint32_t* Bcur = (const uint32_t*)(Bsf + (size_t)cur*BK*B_STRIDE);

        #pragma unroll
        for (int ks = 0; ks < BK/8; ks++) {
            int kb = ks*8;
            uint32_t af[MT][4];
            uint32_t bf[NT][2];
            #pragma unroll
            for (int mt=0; mt<MT; mt++) {
                int r = warpRow*WM + mt*16 + grp;
                af[mt][0] = Acur[(r  )*A_STRIDE + kb + qid    ];
                af[mt][1] = Acur[(r+8)*A_STRIDE + kb + qid    ];
                af[mt][2] = Acur[(r  )*A_STRIDE + kb + qid + 4];
                af[mt][3] = Acur[(r+8)*A_STRIDE + kb + qid + 4];
            }
            #pragma unroll
            for (int nt=0; nt<NT; nt++) {
                int c = warpCol*WN + nt*8 + grp;
                bf[nt][0] = Bcur[(kb + qid    )*B_STRIDE + c];
                bf[nt][1] = Bcur[(kb + qid + 4)*B_STRIDE + c];
            }
            #pragma unroll
            for (int mt=0; mt<MT; mt++)
                #pragma unroll
                for (int nt=0; nt<NT; nt++)
                    mma_tf32(acc[mt][nt], af[mt], bf[nt]);
        }
        __syncthreads();
    }

    #pragma unroll
    for (int mt=0; mt<MT; mt++) {
        int rA = row0 + warpRow*WM + mt*16 + grp;
        int rB = rA + 8;
        #pragma unroll
        for (int nt=0; nt<NT; nt++) {
            int c = col0 + warpCol*WN + nt*8 + qid*2;
            float v0 = acc[mt][nt][0]*alpha;
            float v1 = acc[mt][nt][1]*alpha;
            float v2 = acc[mt][nt][2]*alpha;
            float v3 = acc[mt][nt][3]*alpha;
            if (bias) {
                float2 bb2 = *(const float2*)(bias + c);
                v0 += bb2.x; v1 += bb2.y; v2 += bb2.x; v3 += bb2.y;
            }
            if (relu) {
                v0 = fmaxf(v0,0.f); v1 = fmaxf(v1,0.f);
                v2 = fmaxf(v2,0.f); v3 = fmaxf(v3,0.f);
            }
            if (res) {
                float2 rA2 = *(const float2*)(res + (long long)rA*ldc + c);
                float2 rB2 = *(const float2*)(res + (long long)rB*ldc + c);
                v0 += rA2.x; v1 += rA2.y; v2 += rB2.x; v3 += rB2.y;
            }
            if (round_out) {
                v0 = rndtf(v0); v1 = rndtf(v1); v2 = rndtf(v2); v3 = rndtf(v3);
            }
            *(float2*)(C + (long long)rA*ldc + c) = make_float2(v0, v1);
            *(float2*)(C + (long long)rB*ldc + c) = make_float2(v2, v3);
        }
    }
}

// ---------------- fused flash attention (tf32 mma), causal ----------------
// qkv combined [BT][3072]: q at +0, k at +1024, v at +2048 (all tf32-rounded).
#define QT_S 136
#define KT_S 72
#define VS_S 72
#define PS_S 72
#define FA_SMEM ((64*QT_S + 64*KT_S + 64*VS_S + 128*PS_S)*4)   // 108544 B

__global__ void __launch_bounds__(256, 2)
flash_kernel(const float* __restrict__ qkv, float* __restrict__ attn)
{
    extern __shared__ float fs[];
    float* Qt = fs;                       // [64][QT_S]  (d, row)
    float* Kt = Qt + 64*QT_S;             // [64][KT_S]  (d, s)
    float* Vs = Kt + 64*KT_S;             // [64][VS_S]  (s, d)
    float* Ps = Vs + 64*VS_S;             // [128][PS_S] (row, s)

    int q0 = blockIdx.x * 128;
    int bh = blockIdx.y;
    int b = bh >> 4, h = bh & 15;
    const float* Qg = qkv + (long long)b*SEQ*QKV_LD + h*HSZ;
    const float* Kg = Qg + NEMBD;
    const float* Vg = Qg + 2*NEMBD;

    int tid = threadIdx.x;
    int wid = tid >> 5;
    int lane = tid & 31;
    int grp = lane >> 2;
    int qid = lane & 3;
    int w16 = wid * 16;

    {
        int r  = tid & 127;
        int cb = (tid >> 7) * 4;
        #pragma unroll
        for (int p = 0; p < 8; p++) {
            int c4 = cb + p*8;
            float4 vv = *(const float4*)(Qg + (long long)(q0 + r)*QKV_LD + c4);
            Qt[(c4+0)*QT_S + r] = vv.x;
            Qt[(c4+1)*QT_S + r] = vv.y;
            Qt[(c4+2)*QT_S + r] = vv.z;
            Qt[(c4+3)*QT_S + r] = vv.w;
        }
    }

    float m0 = -INFINITY, m1 = -INFINITY, l0 = 0.f, l1 = 0.f;
    float O[8][4];
    #pragma unroll
    for (int nt=0; nt<8; nt++) { O[nt][0]=0.f; O[nt][1]=0.f; O[nt][2]=0.f; O[nt][3]=0.f; }

    int t0 = q0 + w16 + grp;
    int t1 = t0 + 8;
    int nkv = q0/64 + 2;

    for (int kj = 0; kj < nkv; kj++) {
        int s0 = kj * 64;
        __syncthreads();

        {
            int r  = tid & 63;
            int cb = (tid >> 6) * 4;
            #pragma unroll
            for (int p = 0; p < 4; p++) {
                int c4 = cb + p*16;
                float4 vv = *(const float4*)(Kg + (long long)(s0 + r)*QKV_LD + c4);
                Kt[(c4+0)*KT_S + r] = vv.x;
                Kt[(c4+1)*KT_S + r] = vv.y;
                Kt[(c4+2)*KT_S + r] = vv.z;
                Kt[(c4+3)*KT_S + r] = vv.w;
            }
        }
        for (int ch = tid; ch < 64*16; ch += 256) {
            int r = ch >> 4, c4 = (ch & 15) << 2;
            float4 vv = *(const float4*)(Vg + (long long)(s0 + r)*QKV_LD + c4);
            *(float4*)&Vs[r*VS_S + c4] = vv;
        }
        __syncthreads();

        float sacc[8][4];
        #pragma unroll
        for (int nt=0; nt<8; nt++) { sacc[nt][0]=0.f; sacc[nt][1]=0.f; sacc[nt][2]=0.f; sacc[nt][3]=0.f; }

        const uint32_t* Qtu = (const uint32_t*)Qt;
        const uint32_t* Ktu = (const uint32_t*)Kt;
        #pragma unroll
        for (int ks = 0; ks < 8; ks++) {
            int kb = ks*8;
            uint32_t a[4];
            a[0] = Qtu[(kb+qid  )*QT_S + w16 + grp    ];
            a[1] = Qtu[(kb+qid  )*QT_S + w16 + grp + 8];
            a[2] = Qtu[(kb+qid+4)*QT_S + w16 + grp    ];
            a[3] = Qtu[(kb+qid+4)*QT_S + w16 + grp + 8];
            #pragma unroll
            for (int nt=0; nt<8; nt++) {
                uint32_t bb[2];
                bb[0] = Ktu[(kb+qid  )*KT_S + nt*8 + grp];
                bb[1] = Ktu[(kb+qid+4)*KT_S + nt*8 + grp];
                mma_tf32(sacc[nt], a, bb);
            }
        }

        #pragma unroll
        for (int nt=0; nt<8; nt++) {
            int c = s0 + nt*8 + 2*qid;
            sacc[nt][0] = (c   <= t0) ? sacc[nt][0]*ATT_SCALE : -INFINITY;
            sacc[nt][1] = (c+1 <= t0) ? sacc[nt][1]*ATT_SCALE : -INFINITY;
            sacc[nt][2] = (c   <= t1) ? sacc[nt][2]*ATT_SCALE : -INFINITY;
            sacc[nt][3] = (c+1 <= t1) ? sacc[nt][3]*ATT_SCALE : -INFINITY;
        }

        float ml0 = -INFINITY, ml1 = -INFINITY;
        #pragma unroll
        for (int nt=0; nt<8; nt++) {
            ml0 = fmaxf(ml0, fmaxf(sacc[nt][0], sacc[nt][1]));
            ml1 = fmaxf(ml1, fmaxf(sacc[nt][2], sacc[nt][3]));
        }
        ml0 = fmaxf(ml0, __shfl_xor_sync(0xffffffffu, ml0, 1));
        ml0 = fmaxf(ml0, __shfl_xor_sync(0xffffffffu, ml0, 2));
        ml1 = fmaxf(ml1, __shfl_xor_sync(0xffffffffu, ml1, 1));
        ml1 = fmaxf(ml1, __shfl_xor_sync(0xffffffffu, ml1, 2));

        float mn0 = fmaxf(m0, ml0);
        float mn1 = fmaxf(m1, ml1);
        float al0 = __expf(m0 - mn0);
        float al1 = __expf(m1 - mn1);

        float sum0 = 0.f, sum1 = 0.f;
        #pragma unroll
        for (int nt=0; nt<8; nt++) {
            float p00 = __expf(sacc[nt][0] - mn0);
            float p01 = __expf(sacc[nt][1] - mn0);
            float p10 = __expf(sacc[nt][2] - mn1);
            float p11 = __expf(sacc[nt][3] - mn1);
            sum0 += p00 + p01;
            sum1 += p10 + p11;
            *(float2*)&Ps[(w16+grp  )*PS_S + nt*8 + 2*qid] = make_float2(rndtf(p00), rndtf(p01));
            *(float2*)&Ps[(w16+grp+8)*PS_S + nt*8 + 2*qid] = make_float2(rndtf(p10), rndtf(p11));
        }
        sum0 += __shfl_xor_sync(0xffffffffu, sum0, 1);
        sum0 += __shfl_xor_sync(0xffffffffu, sum0, 2);
        sum1 += __shfl_xor_sync(0xffffffffu, sum1, 1);
        sum1 += __shfl_xor_sync(0xffffffffu, sum1, 2);

        l0 = l0*al0 + sum0;
        l1 = l1*al1 + sum1;
        #pragma unroll
        for (int nt=0; nt<8; nt++) {
            O[nt][0] *= al0; O[nt][1] *= al0;
            O[nt][2] *= al1; O[nt][3] *= al1;
        }
        m0 = mn0; m1 = mn1;
        __syncthreads();

        const uint32_t* Psu = (const uint32_t*)Ps;
        const uint32_t* Vsu = (const uint32_t*)Vs;
        #pragma unroll
        for (int ks = 0; ks < 8; ks++) {
            int kb = ks*8;
            uint32_t a[4];
            a[0] = Psu[(w16+grp  )*PS_S + kb + qid    ];
            a[1] = Psu[(w16+grp+8)*PS_S + kb + qid    ];
            a[2] = Psu[(w16+grp  )*PS_S + kb + qid + 4];
            a[3] = Psu[(w16+grp+8)*PS_S + kb + qid + 4];
            #pragma unroll
            for (int nt=0; nt<8; nt++) {
                uint32_t bb[2];
                bb[0] = Vsu[(kb+qid  )*VS_S + nt*8 + grp];
                bb[1] = Vsu[(kb+qid+4)*VS_S + nt*8 + grp];
                mma_tf32(O[nt], a, bb);
            }
        }
    }

    float inv0 = 1.0f / l0;
    float inv1 = 1.0f / l1;
    float* outA = attn + ((long long)(b*SEQ + t0))*NEMBD + h*HSZ;
    float* outB = attn + ((long long)(b*SEQ + t1))*NEMBD + h*HSZ;
    #pragma unroll
    for (int nt=0; nt<8; nt++) {
        int c = nt*8 + 2*qid;
        *(float2*)(outA + c) = make_float2(rndtf(O[nt][0]*inv0), rndtf(O[nt][1]*inv0));
        *(float2*)(outB + c) = make_float2(rndtf(O[nt][2]*inv1), rndtf(O[nt][3]*inv1));
    }
}

// ---------------- launch ----------------
extern "C" void kernel_launch(void* const* d_in, const int* in_sizes, int n_in,
                              void* d_out, int out_size)
{
    const float* x     = (const float*)d_in[0];
    const float* Wq    = (const float*)d_in[1];
    const float* Wk    = (const float*)d_in[2];
    const float* Wv    = (const float*)d_in[3];
    const float* Wproj = (const float*)d_in[4];
    const float* bproj = (const float*)d_in[5];
    const float* W1    = (const float*)d_in[6];
    const float* b1    = (const float*)d_in[7];
    const float* W2    = (const float*)d_in[8];
    const float* b2    = (const float*)d_in[9];
    const float* ln1w  = (const float*)d_in[10];
    const float* ln1b  = (const float*)d_in[11];
    const float* ln2w  = (const float*)d_in[12];
    const float* ln2b  = (const float*)d_in[13];
    float* out = (float*)d_out;

    float *ph, *pqkv, *pattn, *px2, *pf1, *pwr;
    cudaGetSymbolAddress((void**)&ph,    g_h);
    cudaGetSymbolAddress((void**)&pqkv,  g_qkv);
    cudaGetSymbolAddress((void**)&pattn, g_attn);
    cudaGetSymbolAddress((void**)&px2,   g_x2);
    cudaGetSymbolAddress((void**)&pf1,   g_f1);
    cudaGetSymbolAddress((void**)&pwr,   g_wr);

    const size_t M1 = (size_t)1024*1024;
    float* Wqkv = pwr;             // [1024][3072] row-major (q|k|v)
    float* Wpr  = pwr + 3*M1;      // [1024][1024]
    float* W1r  = pwr + 4*M1;      // [1024][4096]
    float* W2r  = pwr + 8*M1;      // [4096][1024]

    constexpr int ST = 4;
    constexpr size_t SMEM_G128 = (size_t)(ST*128*(16+4) + ST*16*(128+8)) * 4;  // 75776

    auto* kern128 = mma_gemm<128,128,16,64,32,ST>;
    cudaFuncSetAttribute(kern128, cudaFuncAttributeMaxDynamicSharedMemorySize, (int)SMEM_G128);
    cudaFuncSetAttribute(flash_kernel, cudaFuncAttributeMaxDynamicSharedMemorySize, FA_SMEM);

    // 0) tf32-round weights once per replay; Wq/Wk/Wv concatenated into [1024][3072]
    {
        int n4a = (int)(M1/4);         // 1024x1024 -> 256K float4
        int n4b = (int)(4*M1/4);
        round_w_strided<<<(n4a+255)/256, 256>>>(Wq,    Wqkv,          256, QKV_LD, n4a);
        round_w_strided<<<(n4a+255)/256, 256>>>(Wk,    Wqkv + 1024,   256, QKV_LD, n4a);
        round_w_strided<<<(n4a+255)/256, 256>>>(Wv,    Wqkv + 2048,   256, QKV_LD, n4a);
        round_w_strided<<<(n4a+255)/256, 256>>>(Wproj, Wpr,           256, 1024,   n4a);
        round_w_strided<<<(n4b+255)/256, 256>>>(W1,    W1r,          1024, 4096,   n4b);
        round_w_strided<<<(n4b+255)/256, 256>>>(W2,    W2r,           256, 1024,   n4b);
    }

    // 1) LN1 (tf32-rounded)
    ln_kernel<<<BT, 256>>>(x, ln1w, ln1b, ph);

    // 2) fused QKV projection: [BT,1024] @ [1024,3072] -> g_qkv (tf32-rounded)
    kern128<<<dim3(QKV_LD/128, BT/128), 256, SMEM_G128>>>(ph, Wqkv, nullptr, nullptr, pqkv,
        BT, QKV_LD, NEMBD, NEMBD, QKV_LD, QKV_LD, 1.0f, 0, 1);

    // 3) fused flash attention -> g_attn (tf32-rounded)
    flash_kernel<<<dim3(SEQ/128, BATCH*NHEAD), 256, FA_SMEM>>>(pqkv, pattn);

    // 4) x2 = x + attn @ Wproj + bproj
    kern128<<<dim3(NEMBD/128, BT/128), 256, SMEM_G128>>>(pattn, Wpr, bproj, x, px2,
        BT, NEMBD, NEMBD, NEMBD, NEMBD, NEMBD, 1.0f, 0, 0);

    // 5) LN2 (tf32-rounded)
    ln_kernel<<<BT, 256>>>(px2, ln2w, ln2b, ph);

    // 6) f1 = relu(h2 @ W1 + b1) (tf32-rounded)
    kern128<<<dim3(FFDIM/128, BT/128), 256, SMEM_G128>>>(ph, W1r, b1, nullptr, pf1,
        BT, FFDIM, NEMBD, NEMBD, FFDIM, FFDIM, 1.0f, 1, 1);

    // 7) out = x2 + f1 @ W2 + b2
    kern128<<<dim3(NEMBD/128, BT/128), 256, SMEM_G128>>>(pf1, W2r, b2, px2, out,
        BT, NEMBD, FFDIM, FFDIM, NEMBD, NEMBD, 1.0f, 0, 0);
}

// round 13
// speedup vs baseline: 1.7070x; 1.5008x over previous
#include <cuda_runtime.h>
#include <cuda_fp16.h>
#include <math.h>
#include <stdint.h>

#define BATCH 2
#define SEQ   2048
#define NEMBD 1024
#define NHEAD 16
#define HSZ   64
#define FFDIM 4096
#define BT    (BATCH*SEQ)      // 4096 rows
#define QKV_LD 3072
#define LN_EPS 1e-5f
#define ATT_SCALE 0.03125f     // 1024^-0.5

// ---------------- scratch (device globals; no allocation allowed) ----------------
__device__ __half g_h[(size_t)BT*NEMBD];
__device__ __half g_qkv[(size_t)BT*QKV_LD];
__device__ __half g_attn[(size_t)BT*NEMBD];
__device__ float  g_x2[(size_t)BT*NEMBD];
__device__ __half g_f1[(size_t)BT*FFDIM];
__device__ __half g_wr[(size_t)12*1024*1024];  // Wqkv_t[3072][1024] Wpt[1024][1024] W1t[4096][1024] W2t[1024][4096]

// ---------------- helpers ----------------
__device__ __forceinline__ uint32_t f2tf32(float x) {
    uint32_t r;
    asm("cvt.rna.tf32.f32 %0, %1;" : "=r"(r) : "f"(x));
    return r;
}
__device__ __forceinline__ float rndtf(float x) { return __uint_as_float(f2tf32(x)); }

__device__ __forceinline__ void mma_tf32(float* c, const uint32_t* a, const uint32_t* b) {
    asm volatile(
        "mma.sync.aligned.m16n8k8.row.col.f32.tf32.tf32.f32 "
        "{%0,%1,%2,%3}, {%4,%5,%6,%7}, {%8,%9}, {%0,%1,%2,%3};"
        : "+f"(c[0]), "+f"(c[1]), "+f"(c[2]), "+f"(c[3])
        : "r"(a[0]), "r"(a[1]), "r"(a[2]), "r"(a[3]), "r"(b[0]), "r"(b[1]));
}
__device__ __forceinline__ void mma_f16(float* c, const uint32_t* a, const uint32_t* b) {
    asm volatile(
        "mma.sync.aligned.m16n8k16.row.col.f32.f16.f16.f32 "
        "{%0,%1,%2,%3}, {%4,%5,%6,%7}, {%8,%9}, {%0,%1,%2,%3};"
        : "+f"(c[0]), "+f"(c[1]), "+f"(c[2]), "+f"(c[3])
        : "r"(a[0]), "r"(a[1]), "r"(a[2]), "r"(a[3]), "r"(b[0]), "r"(b[1]));
}
__device__ __forceinline__ void cp_async16(uint32_t saddr, const void* gaddr) {
    asm volatile("cp.async.cg.shared.global [%0], [%1], 16;" :: "r"(saddr), "l"(gaddr));
}
__device__ __forceinline__ void cp_commit() {
    asm volatile("cp.async.commit_group;");
}
template<int N>
__device__ __forceinline__ void cp_wait() {
    asm volatile("cp.async.wait_group %0;" :: "n"(N));
}
__device__ __forceinline__ uint32_t smem_u32(const void* p) {
    return (uint32_t)__cvta_generic_to_shared(p);
}

// ---------------- weight transpose + half round: in fp32 [K][N] -> out half [N][K] ----------------
__global__ void transpose_round_h(const float* __restrict__ in, __half* __restrict__ out,
                                  int K, int N)
{
    __shared__ float t[32][33];
    int kb = blockIdx.y*32, nb = blockIdx.x*32;
    int tx = threadIdx.x, ty = threadIdx.y;   // (32, 8)
    #pragma unroll
    for (int i=0;i<32;i+=8)
        t[ty+i][tx] = in[(long long)(kb+ty+i)*N + nb+tx];
    __syncthreads();
    #pragma unroll
    for (int i=0;i<32;i+=8)
        out[(long long)(nb+ty+i)*K + kb+tx] = __float2half_rn(t[tx][ty+i]);
}

// ---------------- LayerNorm: one block per row; fp32 in, half out ----------------
__global__ void ln_kernel(const float* __restrict__ x, const float* __restrict__ w,
                          const float* __restrict__ b, __half* __restrict__ out)
{
    int row = blockIdx.x;
    const float4* xr = (const float4*)(x + (size_t)row*NEMBD);
    int t = threadIdx.x;
    float4 v = xr[t];
    float s  = v.x + v.y + v.z + v.w;
    float s2 = v.x*v.x + v.y*v.y + v.z*v.z + v.w*v.w;
    #pragma unroll
    for (int o = 16; o > 0; o >>= 1) {
        s  += __shfl_xor_sync(0xffffffffu, s,  o);
        s2 += __shfl_xor_sync(0xffffffffu, s2, o);
    }
    __shared__ float ss[8], ss2[8];
    int wid = t >> 5, lid = t & 31;
    if (lid == 0) { ss[wid] = s; ss2[wid] = s2; }
    __syncthreads();
    if (wid == 0) {
        float a  = (lid < 8) ? ss[lid]  : 0.f;
        float a2 = (lid < 8) ? ss2[lid] : 0.f;
        #pragma unroll
        for (int o = 4; o > 0; o >>= 1) {
            a  += __shfl_xor_sync(0xffffffffu, a,  o);
            a2 += __shfl_xor_sync(0xffffffffu, a2, o);
        }
        if (lid == 0) { ss[0] = a; ss2[0] = a2; }
    }
    __syncthreads();
    float mu  = ss[0]  * (1.0f/NEMBD);
    float var = ss2[0] * (1.0f/NEMBD) - mu*mu;
    float inv = rsqrtf(var + LN_EPS);
    const float4 wv = ((const float4*)w)[t];
    const float4 bv = ((const float4*)b)[t];
    __half2 h0 = __floats2half2_rn((v.x - mu)*inv*wv.x + bv.x, (v.y - mu)*inv*wv.y + bv.y);
    __half2 h1 = __floats2half2_rn((v.z - mu)*inv*wv.z + bv.z, (v.w - mu)*inv*wv.w + bv.w);
    __half2* orow = (__half2*)(out + (size_t)row*NEMBD);
    orow[2*t]   = h0;
    orow[2*t+1] = h1;
}

// ---------------- fp16 tensor-core GEMM, cp.async pipeline ----------------
// C[m,n] = sum_k A[m,k]*Bt[n,k] (+bias)(relu)(+res). A half [M][K], Bt half [N][K].
// 128x128 block, 8 warps of 64x32, BK=32, 4-stage cp.async. Row stride 80 B (20 words).
#define ROWB 80
#define HG_STAGE (128*ROWB)                 // 10240 B per A or B stage
template<int STAGES,int OUT_HALF>
__global__ void __launch_bounds__(256, 2)
hgemm(const __half* __restrict__ A, const __half* __restrict__ Bt,
      const float* __restrict__ bias, const float* __restrict__ res,
      void* __restrict__ Cv,
      int M, int N, int K, int ldc, int relu)
{
    constexpr int MT = 4, NT = 4;
    extern __shared__ char smem[];
    uint32_t sA = smem_u32(smem);
    uint32_t sB = sA + STAGES*HG_STAGE;

    int tid = threadIdx.x;
    int wid = tid >> 5;
    int lane = tid & 31;
    int grp = lane >> 2;
    int qid = lane & 3;
    int warpRow = wid >> 2;      // 0..1 -> 64 rows
    int warpCol = wid & 3;       // 0..3 -> 32 cols

    int row0 = blockIdx.y * 128;
    int col0 = blockIdx.x * 128;

    float acc[MT][NT][4];
    #pragma unroll
    for (int i=0;i<MT;i++)
        #pragma unroll
        for (int j=0;j<NT;j++) {
            acc[i][j][0]=0.f; acc[i][j][1]=0.f; acc[i][j][2]=0.f; acc[i][j][3]=0.f;
        }

    int nIter = K / 32;

    // stage fill: A rows 64B (4x16B chunks), B rows 64B. 512 chunks each, 256 thr -> 2 iters.
    auto issue = [&](int s, int buf) {
        #pragma unroll
        for (int t=0; t<2; t++) {
            int ch = tid + t*256;
            int r = ch >> 2;
            int c = ch & 3;
            cp_async16(sA + buf*HG_STAGE + r*ROWB + c*16,
                       A + (long long)(row0 + r)*K + s*32 + c*8);
        }
        #pragma unroll
        for (int t=0; t<2; t++) {
            int ch = tid + t*256;
            int n = ch >> 2;
            int c = ch & 3;
            cp_async16(sB + buf*HG_STAGE + n*ROWB + c*16,
                       Bt + (long long)(col0 + n)*K + s*32 + c*8);
        }
    };

    #pragma unroll
    for (int s=0; s<STAGES-1; s++) {
        if (s < nIter) issue(s, s);
        cp_commit();
    }

    const char* smc = (const char*)smem;
    for (int it = 0; it < nIter; it++) {
        cp_wait<STAGES-2>();
        __syncthreads();

        int cur = it % STAGES;
        int nx = it + STAGES - 1;
        if (nx < nIter) issue(nx, nx % STAGES);
        cp_commit();

        const char* Ac = smc + cur*HG_STAGE;
        const char* Bc = smc + STAGES*HG_STAGE + cur*HG_STAGE;

        #pragma unroll
        for (int ks = 0; ks < 2; ks++) {        // two K=16 steps per BK=32
            int kb = ks*32;                     // byte offset within 64B row half
            uint32_t af[MT][4];
            uint32_t bf[NT][2];
            #pragma unroll
            for (int mt=0; mt<MT; mt++) {
                int rr = warpRow*64 + mt*16 + grp;
                const char* base = Ac + rr*ROWB + kb + qid*4;
                af[mt][0] = *(const uint32_t*)(base);            // (row, k 0..1)
                af[mt][1] = *(const uint32_t*)(base + 8*ROWB);   // (row+8)
                af[mt][2] = *(const uint32_t*)(base + 16);       // (row, k+8)
                af[mt][3] = *(const uint32_t*)(base + 8*ROWB + 16);
            }
            #pragma unroll
            for (int nt=0; nt<NT; nt++) {
                int nn = warpCol*32 + nt*8 + grp;
                const char* base = Bc + nn*ROWB + kb + qid*4;
                bf[nt][0] = *(const uint32_t*)(base);            // (col, k 0..1)
                bf[nt][1] = *(const uint32_t*)(base + 16);       // (col, k+8)
            }
            #pragma unroll
            for (int mt=0; mt<MT; mt++)
                #pragma unroll
                for (int nt=0; nt<NT; nt++)
                    mma_f16(acc[mt][nt], af[mt], bf[nt]);
        }
        __syncthreads();
    }

    // epilogue: C layout c0:(r,c) c1:(r,c+1) c2:(r+8,c) c3:(r+8,c+1)
    #pragma unroll
    for (int mt=0; mt<MT; mt++) {
        int rA = row0 + warpRow*64 + mt*16 + grp;
        int rB = rA + 8;
        #pragma unroll
        for (int nt=0; nt<NT; nt++) {
            int c = col0 + warpCol*32 + nt*8 + qid*2;
            float v0 = acc[mt][nt][0];
            float v1 = acc[mt][nt][1];
            float v2 = acc[mt][nt][2];
            float v3 = acc[mt][nt][3];
            if (bias) {
                float2 bb2 = *(const float2*)(bias + c);
                v0 += bb2.x; v1 += bb2.y; v2 += bb2.x; v3 += bb2.y;
            }
            if (relu) {
                v0 = fmaxf(v0,0.f); v1 = fmaxf(v1,0.f);
                v2 = fmaxf(v2,0.f); v3 = fmaxf(v3,0.f);
            }
            if (res) {
                float2 rA2 = *(const float2*)(res + (long long)rA*ldc + c);
                float2 rB2 = *(const float2*)(res + (long long)rB*ldc + c);
                v0 += rA2.x; v1 += rA2.y; v2 += rB2.x; v3 += rB2.y;
            }
            if (OUT_HALF) {
                __half* C = (__half*)Cv;
                *(__half2*)(C + (long long)rA*ldc + c) = __floats2half2_rn(v0, v1);
                *(__half2*)(C + (long long)rB*ldc + c) = __floats2half2_rn(v2, v3);
            } else {
                float* C = (float*)Cv;
                *(float2*)(C + (long long)rA*ldc + c) = make_float2(v0, v1);
                *(float2*)(C + (long long)rB*ldc + c) = make_float2(v2, v3);
            }
        }
    }
}

// ---------------- fused flash attention (tf32 mma internals), half I/O, causal ----------------
#define QT_S 136
#define KT_S 72
#define VS_S 72
#define PS_S 72
#define FA_SMEM ((64*QT_S + 64*KT_S + 64*VS_S + 128*PS_S)*4)   // 108544 B

__global__ void __launch_bounds__(256, 2)
flash_kernel(const __half* __restrict__ qkv, __half* __restrict__ attn)
{
    extern __shared__ float fs[];
    float* Qt = fs;                       // [64][QT_S]  (d, row)
    float* Kt = Qt + 64*QT_S;             // [64][KT_S]  (d, s)
    float* Vs = Kt + 64*KT_S;             // [64][VS_S]  (s, d)
    float* Ps = Vs + 64*VS_S;             // [128][PS_S] (row, s)

    int q0 = blockIdx.x * 128;
    int bh = blockIdx.y;
    int b = bh >> 4, h = bh & 15;
    const __half* Qg = qkv + (long long)b*SEQ*QKV_LD + h*HSZ;
    const __half* Kg = Qg + NEMBD;
    const __half* Vg = Qg + 2*NEMBD;

    int tid = threadIdx.x;
    int wid = tid >> 5;
    int lane = tid & 31;
    int grp = lane >> 2;
    int qid = lane & 3;
    int w16 = wid * 16;

    // load Q transposed: 2 threads per row, 32 cols each, 4 x uint4 (8 halves)
    {
        int r  = tid & 127;
        int cb = (tid >> 7) * 32;
        #pragma unroll
        for (int p = 0; p < 4; p++) {
            int c8 = cb + p*8;
            uint4 u = *(const uint4*)(Qg + (long long)(q0 + r)*QKV_LD + c8);
            const __half2* hp = (const __half2*)&u;
            #pragma unroll
            for (int j = 0; j < 4; j++) {
                float2 f = __half22float2(hp[j]);
                Qt[(c8 + 2*j    )*QT_S + r] = f.x;
                Qt[(c8 + 2*j + 1)*QT_S + r] = f.y;
            }
        }
    }

    float m0 = -INFINITY, m1 = -INFINITY, l0 = 0.f, l1 = 0.f;
    float O[8][4];
    #pragma unroll
    for (int nt=0; nt<8; nt++) { O[nt][0]=0.f; O[nt][1]=0.f; O[nt][2]=0.f; O[nt][3]=0.f; }

    int t0 = q0 + w16 + grp;
    int t1 = t0 + 8;
    int nkv = q0/64 + 2;

    for (int kj = 0; kj < nkv; kj++) {
        int s0 = kj * 64;
        __syncthreads();

        // K transposed: 4 threads per row, 16 cols each, 2 x uint4
        {
            int r  = tid & 63;
            int cb = (tid >> 6) * 16;
            #pragma unroll
            for (int p = 0; p < 2; p++) {
                int c8 = cb + p*8;
                uint4 u = *(const uint4*)(Kg + (long long)(s0 + r)*QKV_LD + c8);
                const __half2* hp = (const __half2*)&u;
                #pragma unroll
                for (int j = 0; j < 4; j++) {
                    float2 f = __half22float2(hp[j]);
                    Kt[(c8 + 2*j    )*KT_S + r] = f.x;
                    Kt[(c8 + 2*j + 1)*KT_S + r] = f.y;
                }
            }
        }
        // V row-major: 64 rows x 8 chunks of 8 halves
        for (int ch = tid; ch < 64*8; ch += 256) {
            int r = ch >> 3, c8 = (ch & 7) << 3;
            uint4 u = *(const uint4*)(Vg + (long long)(s0 + r)*QKV_LD + c8);
            const __half2* hp = (const __half2*)&u;
            float2 f0 = __half22float2(hp[0]);
            float2 f1 = __half22float2(hp[1]);
            float2 f2 = __half22float2(hp[2]);
            float2 f3 = __half22float2(hp[3]);
            float* vp = &Vs[r*VS_S + c8];
            vp[0]=f0.x; vp[1]=f0.y; vp[2]=f1.x; vp[3]=f1.y;
            vp[4]=f2.x; vp[5]=f2.y; vp[6]=f3.x; vp[7]=f3.y;
        }
        __syncthreads();

        float sacc[8][4];
        #pragma unroll
        for (int nt=0; nt<8; nt++) { sacc[nt][0]=0.f; sacc[nt][1]=0.f; sacc[nt][2]=0.f; sacc[nt][3]=0.f; }

        const uint32_t* Qtu = (const uint32_t*)Qt;
        const uint32_t* Ktu = (const uint32_t*)Kt;
        #pragma unroll
        for (int ks = 0; ks < 8; ks++) {
            int kb = ks*8;
            uint32_t a[4];
            a[0] = Qtu[(kb+qid  )*QT_S + w16 + grp    ];
            a[1] = Qtu[(kb+qid  )*QT_S + w16 + grp + 8];
            a[2] = Qtu[(kb+qid+4)*QT_S + w16 + grp    ];
            a[3] = Qtu[(kb+qid+4)*QT_S + w16 + grp + 8];
            #pragma unroll
            for (int nt=0; nt<8; nt++) {
                uint32_t bb[2];
                bb[0] = Ktu[(kb+qid  )*KT_S + nt*8 + grp];
                bb[1] = Ktu[(kb+qid+4)*KT_S + nt*8 + grp];
                mma_tf32(sacc[nt], a, bb);
            }
        }

        #pragma unroll
        for (int nt=0; nt<8; nt++) {
            int c = s0 + nt*8 + 2*qid;
            sacc[nt][0] = (c   <= t0) ? sacc[nt][0]*ATT_SCALE : -INFINITY;
            sacc[nt][1] = (c+1 <= t0) ? sacc[nt][1]*ATT_SCALE : -INFINITY;
            sacc[nt][2] = (c   <= t1) ? sacc[nt][2]*ATT_SCALE : -INFINITY;
            sacc[nt][3] = (c+1 <= t1) ? sacc[nt][3]*ATT_SCALE : -INFINITY;
        }

        float ml0 = -INFINITY, ml1 = -INFINITY;
        #pragma unroll
        for (int nt=0; nt<8; nt++) {
            ml0 = fmaxf(ml0, fmaxf(sacc[nt][0], sacc[nt][1]));
            ml1 = fmaxf(ml1, fmaxf(sacc[nt][2], sacc[nt][3]));
        }
        ml0 = fmaxf(ml0, __shfl_xor_sync(0xffffffffu, ml0, 1));
        ml0 = fmaxf(ml0, __shfl_xor_sync(0xffffffffu, ml0, 2));
        ml1 = fmaxf(ml1, __shfl_xor_sync(0xffffffffu, ml1, 1));
        ml1 = fmaxf(ml1, __shfl_xor_sync(0xffffffffu, ml1, 2));

        float mn0 = fmaxf(m0, ml0);
        float mn1 = fmaxf(m1, ml1);
        float al0 = __expf(m0 - mn0);
        float al1 = __expf(m1 - mn1);

        float sum0 = 0.f, sum1 = 0.f;
        #pragma unroll
        for (int nt=0; nt<8; nt++) {
            float p00 = __expf(sacc[nt][0] - mn0);
            float p01 = __expf(sacc[nt][1] - mn0);
            float p10 = __expf(sacc[nt][2] - mn1);
            float p11 = __expf(sacc[nt][3] - mn1);
            sum0 += p00 + p01;
            sum1 += p10 + p11;
            *(float2*)&Ps[(w16+grp  )*PS_S + nt*8 + 2*qid] = make_float2(rndtf(p00), rndtf(p01));
            *(float2*)&Ps[(w16+grp+8)*PS_S + nt*8 + 2*qid] = make_float2(rndtf(p10), rndtf(p11));
        }
        sum0 += __shfl_xor_sync(0xffffffffu, sum0, 1);
        sum0 += __shfl_xor_sync(0xffffffffu, sum0, 2);
        sum1 += __shfl_xor_sync(0xffffffffu, sum1, 1);
        sum1 += __shfl_xor_sync(0xffffffffu, sum1, 2);

        l0 = l0*al0 + sum0;
        l1 = l1*al1 + sum1;
        #pragma unroll
        for (int nt=0; nt<8; nt++) {
            O[nt][0] *= al0; O[nt][1] *= al0;
            O[nt][2] *= al1; O[nt][3] *= al1;
        }
        m0 = mn0; m1 = mn1;
        __syncthreads();

        const uint32_t* Psu = (const uint32_t*)Ps;
        const uint32_t* Vsu = (const uint32_t*)Vs;
        #pragma unroll
        for (int ks = 0; ks < 8; ks++) {
            int kb = ks*8;
            uint32_t a[4];
            a[0] = Psu[(w16+grp  )*PS_S + kb + qid    ];
            a[1] = Psu[(w16+grp+8)*PS_S + kb + qid    ];
            a[2] = Psu[(w16+grp  )*PS_S + kb + qid + 4];
            a[3] = Psu[(w16+grp+8)*PS_S + kb + qid + 4];
            #pragma unroll
            for (int nt=0; nt<8; nt++) {
                uint32_t bb[2];
                bb[0] = Vsu[(kb+qid  )*VS_S + nt*8 + grp];
                bb[1] = Vsu[(kb+qid+4)*VS_S + nt*8 + grp];
                mma_tf32(O[nt], a, bb);
            }
        }
    }

    float inv0 = 1.0f / l0;
    float inv1 = 1.0f / l1;
    __half* outA = attn + ((long long)(b*SEQ + t0))*NEMBD + h*HSZ;
    __half* outB = attn + ((long long)(b*SEQ + t1))*NEMBD + h*HSZ;
    #pragma unroll
    for (int nt=0; nt<8; nt++) {
        int c = nt*8 + 2*qid;
        *(__half2*)(outA + c) = __floats2half2_rn(O[nt][0]*inv0, O[nt][1]*inv0);
        *(__half2*)(outB + c) = __floats2half2_rn(O[nt][2]*inv1, O[nt][3]*inv1);
    }
}

// ---------------- launch ----------------
extern "C" void kernel_launch(void* const* d_in, const int* in_sizes, int n_in,
                              void* d_out, int out_size)
{
    const float* x     = (const float*)d_in[0];
    const float* Wq    = (const float*)d_in[1];
    const float* Wk    = (const float*)d_in[2];
    const float* Wv    = (const float*)d_in[3];
    const float* Wproj = (const float*)d_in[4];
    const float* bproj = (const float*)d_in[5];
    const float* W1    = (const float*)d_in[6];
    const float* b1    = (const float*)d_in[7];
    const float* W2    = (const float*)d_in[8];
    const float* b2    = (const float*)d_in[9];
    const float* ln1w  = (const float*)d_in[10];
    const float* ln1b  = (const float*)d_in[11];
    const float* ln2w  = (const float*)d_in[12];
    const float* ln2b  = (const float*)d_in[13];
    float* out = (float*)d_out;

    __half *ph, *pqkv, *pattn, *pf1, *pwr;
    float *px2;
    cudaGetSymbolAddress((void**)&ph,    g_h);
    cudaGetSymbolAddress((void**)&pqkv,  g_qkv);
    cudaGetSymbolAddress((void**)&pattn, g_attn);
    cudaGetSymbolAddress((void**)&px2,   g_x2);
    cudaGetSymbolAddress((void**)&pf1,   g_f1);
    cudaGetSymbolAddress((void**)&pwr,   g_wr);

    const size_t M1 = (size_t)1024*1024;
    __half* Wqkvt = pwr;            // [3072][1024]
    __half* Wpt   = pwr + 3*M1;     // [1024][1024]
    __half* W1t   = pwr + 4*M1;     // [4096][1024]
    __half* W2t   = pwr + 8*M1;     // [1024][4096]

    constexpr int ST = 4;
    constexpr size_t SMEM_G = (size_t)2*ST*HG_STAGE;   // 81920 B

    auto* kh = hgemm<ST,1>;
    auto* kf = hgemm<ST,0>;
    cudaFuncSetAttribute(kh, cudaFuncAttributeMaxDynamicSharedMemorySize, (int)SMEM_G);
    cudaFuncSetAttribute(kf, cudaFuncAttributeMaxDynamicSharedMemorySize, (int)SMEM_G);
    cudaFuncSetAttribute(flash_kernel, cudaFuncAttributeMaxDynamicSharedMemorySize, FA_SMEM);

    // 0) transpose + half-round all weights (once per replay); B operand is [N][K] half
    {
        dim3 blk(32, 8);
        transpose_round_h<<<dim3(32, 32),  blk>>>(Wq,    Wqkvt,        1024, 1024);
        transpose_round_h<<<dim3(32, 32),  blk>>>(Wk,    Wqkvt + M1,   1024, 1024);
        transpose_round_h<<<dim3(32, 32),  blk>>>(Wv,    Wqkvt + 2*M1, 1024, 1024);
        transpose_round_h<<<dim3(32, 32),  blk>>>(Wproj, Wpt,          1024, 1024);
        transpose_round_h<<<dim3(128, 32), blk>>>(W1,    W1t,          1024, 4096);
        transpose_round_h<<<dim3(32, 128), blk>>>(W2,    W2t,          4096, 1024);
    }

    // 1) LN1 -> half
    ln_kernel<<<BT, 256>>>(x, ln1w, ln1b, ph);

    // 2) fused QKV: h[BT,1024] @ Wqkv -> g_qkv (half out)
    kh<<<dim3(QKV_LD/128, BT/128), 256, SMEM_G>>>(ph, Wqkvt, nullptr, nullptr, pqkv,
        BT, QKV_LD, NEMBD, QKV_LD, 0);

    // 3) fused flash attention -> g_attn (half out)
    flash_kernel<<<dim3(SEQ/128, BATCH*NHEAD), 256, FA_SMEM>>>(pqkv, pattn);

    // 4) x2 = x + attn @ Wproj + bproj  (float out)
    kf<<<dim3(NEMBD/128, BT/128), 256, SMEM_G>>>(pattn, Wpt, bproj, x, px2,
        BT, NEMBD, NEMBD, NEMBD, 0);

    // 5) LN2 -> half
    ln_kernel<<<BT, 256>>>(px2, ln2w, ln2b, ph);

    // 6) f1 = relu(h2 @ W1 + b1) (half out)
    kh<<<dim3(FFDIM/128, BT/128), 256, SMEM_G>>>(ph, W1t, b1, nullptr, pf1,
        BT, FFDIM, NEMBD, FFDIM, 1);

    // 7) out = x2 + f1 @ W2 + b2 (float out)
    kf<<<dim3(NEMBD/128, BT/128), 256, SMEM_G>>>(pf1, W2t, b2, px2, out,
        BT, NEMBD, FFDIM, NEMBD, 0);
}

// round 14
// speedup vs baseline: 1.9095x; 1.1186x over previous
#include <cuda_runtime.h>
#include <cuda_fp16.h>
#include <math.h>
#include <stdint.h>

#define BATCH 2
#define SEQ   2048
#define NEMBD 1024
#define NHEAD 16
#define HSZ   64
#define FFDIM 4096
#define BT    (BATCH*SEQ)      // 4096 rows
#define QKV_LD 3072
#define LN_EPS 1e-5f
#define ATT_SCALE 0.03125f     // 1024^-0.5

// ---------------- scratch (device globals; no allocation allowed) ----------------
__device__ __half g_h[(size_t)BT*NEMBD];
__device__ __half g_qkv[(size_t)BT*QKV_LD];
__device__ __half g_attn[(size_t)BT*NEMBD];
__device__ float  g_x2[(size_t)BT*NEMBD];
__device__ __half g_f1[(size_t)BT*FFDIM];
__device__ __half g_wr[(size_t)12*1024*1024];  // Wqkv_t[3072][1024] Wpt[1024][1024] W1t[4096][1024] W2t[1024][4096]

// ---------------- helpers ----------------
__device__ __forceinline__ void mma_f16(float* c, const uint32_t* a, const uint32_t* b) {
    asm volatile(
        "mma.sync.aligned.m16n8k16.row.col.f32.f16.f16.f32 "
        "{%0,%1,%2,%3}, {%4,%5,%6,%7}, {%8,%9}, {%0,%1,%2,%3};"
        : "+f"(c[0]), "+f"(c[1]), "+f"(c[2]), "+f"(c[3])
        : "r"(a[0]), "r"(a[1]), "r"(a[2]), "r"(a[3]), "r"(b[0]), "r"(b[1]));
}
__device__ __forceinline__ void cp_async16(uint32_t saddr, const void* gaddr) {
    asm volatile("cp.async.cg.shared.global [%0], [%1], 16;" :: "r"(saddr), "l"(gaddr));
}
__device__ __forceinline__ void cp_commit() {
    asm volatile("cp.async.commit_group;");
}
template<int N>
__device__ __forceinline__ void cp_wait() {
    asm volatile("cp.async.wait_group %0;" :: "n"(N));
}
__device__ __forceinline__ uint32_t smem_u32(const void* p) {
    return (uint32_t)__cvta_generic_to_shared(p);
}

// ---------------- weight transpose + half round: in fp32 [K][N] -> out half [N][K] ----------------
__global__ void transpose_round_h(const float* __restrict__ in, __half* __restrict__ out,
                                  int K, int N)
{
    __shared__ float t[32][33];
    int kb = blockIdx.y*32, nb = blockIdx.x*32;
    int tx = threadIdx.x, ty = threadIdx.y;   // (32, 8)
    #pragma unroll
    for (int i=0;i<32;i+=8)
        t[ty+i][tx] = in[(long long)(kb+ty+i)*N + nb+tx];
    __syncthreads();
    #pragma unroll
    for (int i=0;i<32;i+=8)
        out[(long long)(nb+ty+i)*K + kb+tx] = __float2half_rn(t[tx][ty+i]);
}

// ---------------- LayerNorm: one block per row; fp32 in, half out ----------------
__global__ void ln_kernel(const float* __restrict__ x, const float* __restrict__ w,
                          const float* __restrict__ b, __half* __restrict__ out)
{
    int row = blockIdx.x;
    const float4* xr = (const float4*)(x + (size_t)row*NEMBD);
    int t = threadIdx.x;
    float4 v = xr[t];
    float s  = v.x + v.y + v.z + v.w;
    float s2 = v.x*v.x + v.y*v.y + v.z*v.z + v.w*v.w;
    #pragma unroll
    for (int o = 16; o > 0; o >>= 1) {
        s  += __shfl_xor_sync(0xffffffffu, s,  o);
        s2 += __shfl_xor_sync(0xffffffffu, s2, o);
    }
    __shared__ float ss[8], ss2[8];
    int wid = t >> 5, lid = t & 31;
    if (lid == 0) { ss[wid] = s; ss2[wid] = s2; }
    __syncthreads();
    if (wid == 0) {
        float a  = (lid < 8) ? ss[lid]  : 0.f;
        float a2 = (lid < 8) ? ss2[lid] : 0.f;
        #pragma unroll
        for (int o = 4; o > 0; o >>= 1) {
            a  += __shfl_xor_sync(0xffffffffu, a,  o);
            a2 += __shfl_xor_sync(0xffffffffu, a2, o);
        }
        if (lid == 0) { ss[0] = a; ss2[0] = a2; }
    }
    __syncthreads();
    float mu  = ss[0]  * (1.0f/NEMBD);
    float var = ss2[0] * (1.0f/NEMBD) - mu*mu;
    float inv = rsqrtf(var + LN_EPS);
    const float4 wv = ((const float4*)w)[t];
    const float4 bv = ((const float4*)b)[t];
    __half2 h0 = __floats2half2_rn((v.x - mu)*inv*wv.x + bv.x, (v.y - mu)*inv*wv.y + bv.y);
    __half2 h1 = __floats2half2_rn((v.z - mu)*inv*wv.z + bv.z, (v.w - mu)*inv*wv.w + bv.w);
    __half2* orow = (__half2*)(out + (size_t)row*NEMBD);
    orow[2*t]   = h0;
    orow[2*t+1] = h1;
}

// ---------------- fp16 tensor-core GEMM, cp.async pipeline (R13 proven) ----------------
#define ROWB 80
#define HG_STAGE (128*ROWB)
template<int STAGES,int OUT_HALF>
__global__ void __launch_bounds__(256, 2)
hgemm(const __half* __restrict__ A, const __half* __restrict__ Bt,
      const float* __restrict__ bias, const float* __restrict__ res,
      void* __restrict__ Cv,
      int M, int N, int K, int ldc, int relu)
{
    constexpr int MT = 4, NT = 4;
    extern __shared__ char smem[];
    uint32_t sA = smem_u32(smem);
    uint32_t sB = sA + STAGES*HG_STAGE;

    int tid = threadIdx.x;
    int wid = tid >> 5;
    int lane = tid & 31;
    int grp = lane >> 2;
    int qid = lane & 3;
    int warpRow = wid >> 2;
    int warpCol = wid & 3;

    int row0 = blockIdx.y * 128;
    int col0 = blockIdx.x * 128;

    float acc[MT][NT][4];
    #pragma unroll
    for (int i=0;i<MT;i++)
        #pragma unroll
        for (int j=0;j<NT;j++) {
            acc[i][j][0]=0.f; acc[i][j][1]=0.f; acc[i][j][2]=0.f; acc[i][j][3]=0.f;
        }

    int nIter = K / 32;

    auto issue = [&](int s, int buf) {
        #pragma unroll
        for (int t=0; t<2; t++) {
            int ch = tid + t*256;
            int r = ch >> 2;
            int c = ch & 3;
            cp_async16(sA + buf*HG_STAGE + r*ROWB + c*16,
                       A + (long long)(row0 + r)*K + s*32 + c*8);
        }
        #pragma unroll
        for (int t=0; t<2; t++) {
            int ch = tid + t*256;
            int n = ch >> 2;
            int c = ch & 3;
            cp_async16(sB + buf*HG_STAGE + n*ROWB + c*16,
                       Bt + (long long)(col0 + n)*K + s*32 + c*8);
        }
    };

    #pragma unroll
    for (int s=0; s<STAGES-1; s++) {
        if (s < nIter) issue(s, s);
        cp_commit();
    }

    const char* smc = (const char*)smem;
    for (int it = 0; it < nIter; it++) {
        cp_wait<STAGES-2>();
        __syncthreads();

        int cur = it % STAGES;
        int nx = it + STAGES - 1;
        if (nx < nIter) issue(nx, nx % STAGES);
        cp_commit();

        const char* Ac = smc + cur*HG_STAGE;
        const char* Bc = smc + STAGES*HG_STAGE + cur*HG_STAGE;

        #pragma unroll
        for (int ks = 0; ks < 2; ks++) {
            int kb = ks*32;
            uint32_t af[MT][4];
            uint32_t bf[NT][2];
            #pragma unroll
            for (int mt=0; mt<MT; mt++) {
                int rr = warpRow*64 + mt*16 + grp;
                const char* base = Ac + rr*ROWB + kb + qid*4;
                af[mt][0] = *(const uint32_t*)(base);
                af[mt][1] = *(const uint32_t*)(base + 8*ROWB);
                af[mt][2] = *(const uint32_t*)(base + 16);
                af[mt][3] = *(const uint32_t*)(base + 8*ROWB + 16);
            }
            #pragma unroll
            for (int nt=0; nt<NT; nt++) {
                int nn = warpCol*32 + nt*8 + grp;
                const char* base = Bc + nn*ROWB + kb + qid*4;
                bf[nt][0] = *(const uint32_t*)(base);
                bf[nt][1] = *(const uint32_t*)(base + 16);
            }
            #pragma unroll
            for (int mt=0; mt<MT; mt++)
                #pragma unroll
                for (int nt=0; nt<NT; nt++)
                    mma_f16(acc[mt][nt], af[mt], bf[nt]);
        }
        __syncthreads();
    }

    #pragma unroll
    for (int mt=0; mt<MT; mt++) {
        int rA = row0 + warpRow*64 + mt*16 + grp;
        int rB = rA + 8;
        #pragma unroll
        for (int nt=0; nt<NT; nt++) {
            int c = col0 + warpCol*32 + nt*8 + qid*2;
            float v0 = acc[mt][nt][0];
            float v1 = acc[mt][nt][1];
            float v2 = acc[mt][nt][2];
            float v3 = acc[mt][nt][3];
            if (bias) {
                float2 bb2 = *(const float2*)(bias + c);
                v0 += bb2.x; v1 += bb2.y; v2 += bb2.x; v3 += bb2.y;
            }
            if (relu) {
                v0 = fmaxf(v0,0.f); v1 = fmaxf(v1,0.f);
                v2 = fmaxf(v2,0.f); v3 = fmaxf(v3,0.f);
            }
            if (res) {
                float2 rA2 = *(const float2*)(res + (long long)rA*ldc + c);
                float2 rB2 = *(const float2*)(res + (long long)rB*ldc + c);
                v0 += rA2.x; v1 += rA2.y; v2 += rB2.x; v3 += rB2.y;
            }
            if (OUT_HALF) {
                __half* C = (__half*)Cv;
                *(__half2*)(C + (long long)rA*ldc + c) = __floats2half2_rn(v0, v1);
                *(__half2*)(C + (long long)rB*ldc + c) = __floats2half2_rn(v2, v3);
            } else {
                float* C = (float*)Cv;
                *(float2*)(C + (long long)rA*ldc + c) = make_float2(v0, v1);
                *(float2*)(C + (long long)rB*ldc + c) = make_float2(v2, v3);
            }
        }
    }
}

// ---------------- fused flash attention, all-f16 mma, causal ----------------
// Smem (half): Qs[128][72] row-major (row,d); Ks[64][72] (s,d); Vt[64][72] (d,s); Ps[128][72] (row,s)
#define FH_S 72
#define FA_SMEM ((128*FH_S + 64*FH_S + 64*FH_S + 128*FH_S)*2)   // 55296 B

__global__ void __launch_bounds__(256, 2)
flash_kernel(const __half* __restrict__ qkv, __half* __restrict__ attn)
{
    extern __shared__ __half fh[];
    __half* Qs = fh;                      // [128][FH_S]
    __half* Ks = Qs + 128*FH_S;           // [64][FH_S]
    __half* Vt = Ks + 64*FH_S;            // [64][FH_S]  (d, s)
    __half* Ps = Vt + 64*FH_S;            // [128][FH_S]

    int q0 = blockIdx.x * 128;
    int bh = blockIdx.y;
    int b = bh >> 4, h = bh & 15;
    const __half* Qg = qkv + (long long)b*SEQ*QKV_LD + h*HSZ;
    const __half* Kg = Qg + NEMBD;
    const __half* Vg = Qg + 2*NEMBD;

    int tid = threadIdx.x;
    int wid = tid >> 5;
    int lane = tid & 31;
    int grp = lane >> 2;
    int qid = lane & 3;
    int w16 = wid * 16;

    // load Q straight copy (row-major): 128 rows x 8 uint4 chunks
    #pragma unroll
    for (int t = 0; t < 4; t++) {
        int ch = tid + t*256;
        int r = ch >> 3, c8 = (ch & 7) << 3;
        *(uint4*)&Qs[r*FH_S + c8] = *(const uint4*)(Qg + (long long)(q0 + r)*QKV_LD + c8);
    }

    float m0 = -INFINITY, m1 = -INFINITY, l0 = 0.f, l1 = 0.f;
    float O[8][4];
    #pragma unroll
    for (int nt=0; nt<8; nt++) { O[nt][0]=0.f; O[nt][1]=0.f; O[nt][2]=0.f; O[nt][3]=0.f; }

    int t0 = q0 + w16 + grp;
    int t1 = t0 + 8;
    int nkv = q0/64 + 2;

    for (int kj = 0; kj < nkv; kj++) {
        int s0 = kj * 64;
        __syncthreads();   // previous iter's PV done before overwriting K/V

        // K straight copy (row-major [s][d]): 64 x 8 chunks = 512, 2 per thread
        #pragma unroll
        for (int t = 0; t < 2; t++) {
            int ch = tid + t*256;
            int r = ch >> 3, c8 = (ch & 7) << 3;
            *(uint4*)&Ks[r*FH_S + c8] = *(const uint4*)(Kg + (long long)(s0 + r)*QKV_LD + c8);
        }
        // V transposed into Vt[d][s]: read 8 halves along d, scatter
        #pragma unroll
        for (int t = 0; t < 2; t++) {
            int ch = tid + t*256;
            int s = ch >> 3, d0 = (ch & 7) << 3;
            uint4 u = *(const uint4*)(Vg + (long long)(s0 + s)*QKV_LD + d0);
            const __half* hp = (const __half*)&u;
            #pragma unroll
            for (int j = 0; j < 8; j++)
                Vt[(d0 + j)*FH_S + s] = hp[j];
        }
        __syncthreads();

        // ---- S = Q K^T (f16 mma, warp: 16 rows x 64 cols, K=64 -> 4 k-steps) ----
        float sacc[8][4];
        #pragma unroll
        for (int nt=0; nt<8; nt++) { sacc[nt][0]=0.f; sacc[nt][1]=0.f; sacc[nt][2]=0.f; sacc[nt][3]=0.f; }

        #pragma unroll
        for (int ks = 0; ks < 4; ks++) {
            int kb = ks*16;           // d offset
            uint32_t a[4];
            const __half* Abase = &Qs[(w16 + grp)*FH_S + kb + 2*qid];
            a[0] = *(const uint32_t*)(Abase);
            a[1] = *(const uint32_t*)(Abase + 8*FH_S);
            a[2] = *(const uint32_t*)(Abase + 8);
            a[3] = *(const uint32_t*)(Abase + 8*FH_S + 8);
            #pragma unroll
            for (int nt=0; nt<8; nt++) {
                const __half* Bbase = &Ks[(nt*8 + grp)*FH_S + kb + 2*qid];
                uint32_t bb[2];
                bb[0] = *(const uint32_t*)(Bbase);
                bb[1] = *(const uint32_t*)(Bbase + 8);
                mma_f16(sacc[nt], a, bb);
            }
        }

        // ---- mask + scale ----
        #pragma unroll
        for (int nt=0; nt<8; nt++) {
            int c = s0 + nt*8 + 2*qid;
            sacc[nt][0] = (c   <= t0) ? sacc[nt][0]*ATT_SCALE : -INFINITY;
            sacc[nt][1] = (c+1 <= t0) ? sacc[nt][1]*ATT_SCALE : -INFINITY;
            sacc[nt][2] = (c   <= t1) ? sacc[nt][2]*ATT_SCALE : -INFINITY;
            sacc[nt][3] = (c+1 <= t1) ? sacc[nt][3]*ATT_SCALE : -INFINITY;
        }

        float ml0 = -INFINITY, ml1 = -INFINITY;
        #pragma unroll
        for (int nt=0; nt<8; nt++) {
            ml0 = fmaxf(ml0, fmaxf(sacc[nt][0], sacc[nt][1]));
            ml1 = fmaxf(ml1, fmaxf(sacc[nt][2], sacc[nt][3]));
        }
        ml0 = fmaxf(ml0, __shfl_xor_sync(0xffffffffu, ml0, 1));
        ml0 = fmaxf(ml0, __shfl_xor_sync(0xffffffffu, ml0, 2));
        ml1 = fmaxf(ml1, __shfl_xor_sync(0xffffffffu, ml1, 1));
        ml1 = fmaxf(ml1, __shfl_xor_sync(0xffffffffu, ml1, 2));

        float mn0 = fmaxf(m0, ml0);
        float mn1 = fmaxf(m1, ml1);
        float al0 = __expf(m0 - mn0);
        float al1 = __expf(m1 - mn1);

        float sum0 = 0.f, sum1 = 0.f;
        #pragma unroll
        for (int nt=0; nt<8; nt++) {
            float p00 = __expf(sacc[nt][0] - mn0);
            float p01 = __expf(sacc[nt][1] - mn0);
            float p10 = __expf(sacc[nt][2] - mn1);
            float p11 = __expf(sacc[nt][3] - mn1);
            sum0 += p00 + p01;
            sum1 += p10 + p11;
            int c = nt*8 + 2*qid;
            *(__half2*)&Ps[(w16+grp  )*FH_S + c] = __floats2half2_rn(p00, p01);
            *(__half2*)&Ps[(w16+grp+8)*FH_S + c] = __floats2half2_rn(p10, p11);
        }
        sum0 += __shfl_xor_sync(0xffffffffu, sum0, 1);
        sum0 += __shfl_xor_sync(0xffffffffu, sum0, 2);
        sum1 += __shfl_xor_sync(0xffffffffu, sum1, 1);
        sum1 += __shfl_xor_sync(0xffffffffu, sum1, 2);

        l0 = l0*al0 + sum0;
        l1 = l1*al1 + sum1;
        #pragma unroll
        for (int nt=0; nt<8; nt++) {
            O[nt][0] *= al0; O[nt][1] *= al0;
            O[nt][2] *= al1; O[nt][3] *= al1;
        }
        m0 = mn0; m1 = mn1;
        __syncwarp();

        // ---- O += P V (f16 mma, warp: 16 rows x 64 d, K=64 s -> 4 k-steps) ----
        #pragma unroll
        for (int ks = 0; ks < 4; ks++) {
            int kb = ks*16;           // s offset
            uint32_t a[4];
            const __half* Abase = &Ps[(w16 + grp)*FH_S + kb + 2*qid];
            a[0] = *(const uint32_t*)(Abase);
            a[1] = *(const uint32_t*)(Abase + 8*FH_S);
            a[2] = *(const uint32_t*)(Abase + 8);
            a[3] = *(const uint32_t*)(Abase + 8*FH_S + 8);
            #pragma unroll
            for (int nt=0; nt<8; nt++) {
                const __half* Bbase = &Vt[(nt*8 + grp)*FH_S + kb + 2*qid];
                uint32_t bb[2];
                bb[0] = *(const uint32_t*)(Bbase);
                bb[1] = *(const uint32_t*)(Bbase + 8);
                mma_f16(O[nt], a, bb);
            }
        }
    }

    float inv0 = 1.0f / l0;
    float inv1 = 1.0f / l1;
    __half* outA = attn + ((long long)(b*SEQ + t0))*NEMBD + h*HSZ;
    __half* outB = attn + ((long long)(b*SEQ + t1))*NEMBD + h*HSZ;
    #pragma unroll
    for (int nt=0; nt<8; nt++) {
        int c = nt*8 + 2*qid;
        *(__half2*)(outA + c) = __floats2half2_rn(O[nt][0]*inv0, O[nt][1]*inv0);
        *(__half2*)(outB + c) = __floats2half2_rn(O[nt][2]*inv1, O[nt][3]*inv1);
    }
}

// ---------------- launch ----------------
extern "C" void kernel_launch(void* const* d_in, const int* in_sizes, int n_in,
                              void* d_out, int out_size)
{
    const float* x     = (const float*)d_in[0];
    const float* Wq    = (const float*)d_in[1];
    const float* Wk    = (const float*)d_in[2];
    const float* Wv    = (const float*)d_in[3];
    const float* Wproj = (const float*)d_in[4];
    const float* bproj = (const float*)d_in[5];
    const float* W1    = (const float*)d_in[6];
    const float* b1    = (const float*)d_in[7];
    const float* W2    = (const float*)d_in[8];
    const float* b2    = (const float*)d_in[9];
    const float* ln1w  = (const float*)d_in[10];
    const float* ln1b  = (const float*)d_in[11];
    const float* ln2w  = (const float*)d_in[12];
    const float* ln2b  = (const float*)d_in[13];
    float* out = (float*)d_out;

    __half *ph, *pqkv, *pattn, *pf1, *pwr;
    float *px2;
    cudaGetSymbolAddress((void**)&ph,    g_h);
    cudaGetSymbolAddress((void**)&pqkv,  g_qkv);
    cudaGetSymbolAddress((void**)&pattn, g_attn);
    cudaGetSymbolAddress((void**)&px2,   g_x2);
    cudaGetSymbolAddress((void**)&pf1,   g_f1);
    cudaGetSymbolAddress((void**)&pwr,   g_wr);

    const size_t M1 = (size_t)1024*1024;
    __half* Wqkvt = pwr;            // [3072][1024]
    __half* Wpt   = pwr + 3*M1;     // [1024][1024]
    __half* W1t   = pwr + 4*M1;     // [4096][1024]
    __half* W2t   = pwr + 8*M1;     // [1024][4096]

    constexpr int ST = 4;
    constexpr size_t SMEM_G = (size_t)2*ST*HG_STAGE;   // 81920 B

    auto* kh = hgemm<ST,1>;
    auto* kf = hgemm<ST,0>;
    cudaFuncSetAttribute(kh, cudaFuncAttributeMaxDynamicSharedMemorySize, (int)SMEM_G);
    cudaFuncSetAttribute(kf, cudaFuncAttributeMaxDynamicSharedMemorySize, (int)SMEM_G);
    cudaFuncSetAttribute(flash_kernel, cudaFuncAttributeMaxDynamicSharedMemorySize, (int)FA_SMEM);

    // 0) transpose + half-round all weights (once per replay)
    {
        dim3 blk(32, 8);
        transpose_round_h<<<dim3(32, 32),  blk>>>(Wq,    Wqkvt,        1024, 1024);
        transpose_round_h<<<dim3(32, 32),  blk>>>(Wk,    Wqkvt + M1,   1024, 1024);
        transpose_round_h<<<dim3(32, 32),  blk>>>(Wv,    Wqkvt + 2*M1, 1024, 1024);
        transpose_round_h<<<dim3(32, 32),  blk>>>(Wproj, Wpt,          1024, 1024);
        transpose_round_h<<<dim3(128, 32), blk>>>(W1,    W1t,          1024, 4096);
        transpose_round_h<<<dim3(32, 128), blk>>>(W2,    W2t,          4096, 1024);
    }

    // 1) LN1 -> half
    ln_kernel<<<BT, 256>>>(x, ln1w, ln1b, ph);

    // 2) fused QKV: h[BT,1024] @ Wqkv -> g_qkv (half out)
    kh<<<dim3(QKV_LD/128, BT/128), 256, SMEM_G>>>(ph, Wqkvt, nullptr, nullptr, pqkv,
        BT, QKV_LD, NEMBD, QKV_LD, 0);

    // 3) fused flash attention (all-f16 mma) -> g_attn (half out)
    flash_kernel<<<dim3(SEQ/128, BATCH*NHEAD), 256, FA_SMEM>>>(pqkv, pattn);

    // 4) x2 = x + attn @ Wproj + bproj  (float out)
    kf<<<dim3(NEMBD/128, BT/128), 256, SMEM_G>>>(pattn, Wpt, bproj, x, px2,
        BT, NEMBD, NEMBD, NEMBD, 0);

    // 5) LN2 -> half
    ln_kernel<<<BT, 256>>>(px2, ln2w, ln2b, ph);

    // 6) f1 = relu(h2 @ W1 + b1) (half out)
    kh<<<dim3(FFDIM/128, BT/128), 256, SMEM_G>>>(ph, W1t, b1, nullptr, pf1,
        BT, FFDIM, NEMBD, FFDIM, 1);

    // 7) out = x2 + f1 @ W2 + b2 (float out)
    kf<<<dim3(NEMBD/128, BT/128), 256, SMEM_G>>>(pf1, W2t, b2, px2, out,
        BT, NEMBD, FFDIM, NEMBD, 0);
}